// round 13
// baseline (speedup 1.0000x reference)
#include <cuda_runtime.h>
#include <cuda_bf16.h>
#include <cuda_fp16.h>
#include <math.h>
#include <stdint.h>

// ---------------------------------------------------------------------------
// lstm_gcn round 13: fused single-pass fp16 GEMM + LSTM cell epilogue.
// Interleaved weights (col j = q*4+gate) -> tile holds all 4 gates; raw acc
// staged to smem fp16; cell (MUFU.TANH) in-kernel; ping-pong h buffers
// (no cross-CTA race). Kills fp16 gates round-trip + 16 cell launches.
// ---------------------------------------------------------------------------

#define MAXN   50000
#define MAXSEQ 16
#define DIM    128
#define NG     512

__device__ float  g_h[MAXN * DIM];
__device__ float  g_c[MAXN * DIM];
__device__ float  g_t1[MAXN * DIM];
__device__ float  g_t2[MAXN * DIM];
__device__ float  g_bperm[NG];
__device__ int    g_eflag;

__device__ __half g_xh[MAXSEQ * MAXN * DIM];   // x in fp16
__device__ __half g_hh[2][MAXN * DIM];         // h fp16, ping-pong
__device__ __half g_wc[NG * 256];              // interleaved [Wih|Whh] fp16

// ------------------------------ helpers ------------------------------------
__device__ __forceinline__ uint32_t smem_u32(const void* p) {
    uint32_t a;
    asm("{ .reg .u64 t; cvta.to.shared.u64 t, %1; cvt.u32.u64 %0, t; }"
        : "=r"(a) : "l"(p));
    return a;
}

__device__ __forceinline__ void ldsm4(uint32_t* r, uint32_t addr) {
    asm volatile("ldmatrix.sync.aligned.m8n8.x4.shared.b16 {%0,%1,%2,%3}, [%4];"
                 : "=r"(r[0]), "=r"(r[1]), "=r"(r[2]), "=r"(r[3]) : "r"(addr));
}

__device__ __forceinline__ void mma_f16(float* d, const uint32_t* a,
                                        const uint32_t* b) {
    asm volatile(
        "mma.sync.aligned.m16n8k16.row.col.f32.f16.f16.f32 "
        "{%0,%1,%2,%3}, {%4,%5,%6,%7}, {%8,%9}, {%0,%1,%2,%3};"
        : "+f"(d[0]), "+f"(d[1]), "+f"(d[2]), "+f"(d[3])
        : "r"(a[0]), "r"(a[1]), "r"(a[2]), "r"(a[3]), "r"(b[0]), "r"(b[1]));
}

__device__ __forceinline__ void cp_async16(uint32_t dst, const void* src) {
    asm volatile("cp.async.cg.shared.global [%0], [%1], 16;"
                 :: "r"(dst), "l"(src));
}
__device__ __forceinline__ void cp_commit() {
    asm volatile("cp.async.commit_group;");
}
__device__ __forceinline__ void cp_wait1() {
    asm volatile("cp.async.wait_group 1;");
}
__device__ __forceinline__ void cp_wait0() {
    asm volatile("cp.async.wait_group 0;");
}

// HW tanh (MUFU.TANH), rel err ~2^-11
__device__ __forceinline__ float tanh_fast(float x) {
    float y;
    asm("tanh.approx.f32 %0, %1;" : "=f"(y) : "f"(x));
    return y;
}
__device__ __forceinline__ float sigf(float x) {
    return fmaf(tanh_fast(0.5f * x), 0.5f, 0.5f);
}

// vector reduction (sm_90+): 4 floats in one op
__device__ __forceinline__ void red_add_v4(float* addr, float4 v) {
    asm volatile("red.global.add.v4.f32 [%0], {%1, %2, %3, %4};"
                 :: "l"(addr), "f"(v.x), "f"(v.y), "f"(v.z), "f"(v.w)
                 : "memory");
}

// ------------------------------ edge dtype detect --------------------------
__global__ void detect_edge_dtype_k(const int* __restrict__ e32, long long n32,
                                    int* __restrict__ flag) {
    __shared__ int nz;
    if (threadIdx.x == 0) nz = 0;
    __syncthreads();
    for (long long i = threadIdx.x; i < 4096; i += blockDim.x) {
        long long idx = 2 * i + 1;
        if (idx < n32 && e32[idx] != 0) atomicOr(&nz, 1);
    }
    __syncthreads();
    if (threadIdx.x == 0) *flag = (nz == 0) ? 1 : 0;
}

// ------------------------------ small kernels ------------------------------
__global__ void fill_zero_k(float* __restrict__ p, int n) {
    int i = blockIdx.x * blockDim.x + threadIdx.x;
    if (i < n) p[i] = 0.0f;
}

// permuted bias: j = q*4+gate  <->  old row (j&3)*128 + (j>>2)
__global__ void bias_perm_k(const float* __restrict__ a, const float* __restrict__ b,
                            float* __restrict__ o) {
    int j = threadIdx.x;   // 512 threads
    int old = (j & 3) * 128 + (j >> 2);
    o[j] = a[old] + b[old];
}

__global__ void fill_bias_k(float* __restrict__ out, const float* __restrict__ b, int total) {
    int i = blockIdx.x * blockDim.x + threadIdx.x;
    if (i < total) out[i] = b[i & (DIM - 1)];
}

__global__ void relu_bias_k(const float* __restrict__ in, const float* __restrict__ b,
                            float* __restrict__ out, int total) {
    int i = blockIdx.x * blockDim.x + threadIdx.x;
    if (i < total) {
        float v = in[i] + b[i & (DIM - 1)];
        out[i] = v > 0.0f ? v : 0.0f;
    }
}

// fp32 -> fp16 convert (vectorized x4)
__global__ void cvt_half_k(const float* __restrict__ src,
                           __half* __restrict__ dst, int n4) {
    int i = blockIdx.x * blockDim.x + threadIdx.x;
    if (i >= n4) return;
    float4 v = ((const float4*)src)[i];
    __half2* dp = (__half2*)(dst + (size_t)i * 4);
    dp[0] = __floats2half2_rn(v.x, v.y);
    dp[1] = __floats2half2_rn(v.z, v.w);
}

// interleaved Wcat: new row j (= q*4+gate) <- old gate row (j&3)*128+(j>>2)
__global__ void build_wcat_k(const float* __restrict__ wih, const float* __restrict__ whh,
                             __half* __restrict__ wc) {
    int idx = blockIdx.x * blockDim.x + threadIdx.x;
    if (idx >= NG * 256) return;
    int j = idx >> 8, k = idx & 255;
    int old = (j & 3) * 128 + (j >> 2);
    float v = (k < 128) ? wih[old * 128 + k] : whh[old * 128 + (k - 128)];
    wc[idx] = __float2half_rn(v);
}

// ---------------------------------------------------------------------------
// Fused fp16 gate GEMM + LSTM cell.
// Block tile 128(M) x 128(N interleaved), 8 warps, BK=32, double-buffered
// cp.async, 8 k-iterations. Epilogue stages acc->smem fp16, then cell with
// coalesced c / h(fp16 pong) / h(fp32 last step) I/O. Exclusive (row,q)
// ownership; reads hh_in, writes hh_out (ping-pong) -> race-free.
// ---------------------------------------------------------------------------
#define ROWB 80     // bytes per smem row (32 fp16 data + pad)
#define ATILE 10240 // 128 * 80
#define NITER 8
#define GST 132     // epilogue gates smem stride in halves

__global__ __launch_bounds__(256, 2) void gemm_lstm_fused(
    const __half* __restrict__ xh, const __half* __restrict__ hh_in,
    const __half* __restrict__ wc,
    const float* __restrict__ bperm,
    float* __restrict__ c, float* __restrict__ hfp,
    __half* __restrict__ hh_out, int M, int write_h) {
    __shared__ __align__(128) char sm[4 * ATILE];  // A0 A1 B0 B1 / epi gates

    int tid  = threadIdx.x;
    int wid  = tid >> 5;
    int lane = tid & 31;
    int m0 = blockIdx.x * 128;
    int n0 = blockIdx.y * 128;

    uint32_t sbase = smem_u32(sm);
    int wm = (wid >> 2) * 64;
    int wn = (wid & 3) * 32;

    int a_row  = (lane & 7) + ((lane >> 3) & 1) * 8;
    int a_kch  = lane >> 4;
    int b_row  = (lane & 7) + (lane >> 4) * 8;
    int b_kch  = (lane >> 3) & 1;

    int r0c = tid >> 2;
    int ch  = (tid & 3);

    float acc[4][4][4];
#pragma unroll
    for (int i = 0; i < 4; ++i)
#pragma unroll
        for (int j = 0; j < 4; ++j)
#pragma unroll
            for (int q = 0; q < 4; ++q) acc[i][j][q] = 0.0f;

    auto issue = [&](int i, int b) {
        int kc = i & 7;             // 0..7 over K=256
        const __half* Ap = (kc < 4) ? xh : hh_in;
        int ka = (kc & 3) * 32;
        int kb = kc * 32;

        uint32_t dA = sbase + b * ATILE;
        uint32_t dB = sbase + 2 * ATILE + b * ATILE;
#pragma unroll
        for (int it = 0; it < 2; ++it) {
            int r = r0c + it * 64;
            int gm = m0 + r;
            const __half* src =
                Ap + (size_t)(gm < M ? gm : 0) * DIM + ka + ch * 8;
            cp_async16(dA + r * ROWB + ch * 16, src);
        }
#pragma unroll
        for (int it = 0; it < 2; ++it) {
            int r = r0c + it * 64;
            const __half* src = wc + (size_t)(n0 + r) * 256 + kb + ch * 8;
            cp_async16(dB + r * ROWB + ch * 16, src);
        }
        cp_commit();
    };

    issue(0, 0);

    for (int i = 0; i < NITER; ++i) {
        if (i + 1 < NITER) issue(i + 1, (i + 1) & 1);
        if (i + 1 < NITER) cp_wait1(); else cp_wait0();
        __syncthreads();

        int b = i & 1;
        uint32_t sA = sbase + b * ATILE;
        uint32_t sB = sbase + 2 * ATILE + b * ATILE;

#pragma unroll
        for (int k16 = 0; k16 < 2; ++k16) {
            uint32_t afr[4][4];
            uint32_t bfr[2][4];
#pragma unroll
            for (int fm = 0; fm < 4; ++fm) {
                uint32_t addr = sA + (wm + fm * 16 + a_row) * ROWB
                              + (k16 * 2 + a_kch) * 16;
                ldsm4(afr[fm], addr);
            }
#pragma unroll
            for (int fn2 = 0; fn2 < 2; ++fn2) {
                uint32_t addr = sB + (wn + fn2 * 16 + b_row) * ROWB
                              + (k16 * 2 + b_kch) * 16;
                ldsm4(bfr[fn2], addr);
            }
#pragma unroll
            for (int fm = 0; fm < 4; ++fm) {
#pragma unroll
                for (int fn = 0; fn < 4; ++fn)
                    mma_f16(acc[fm][fn], afr[fm], &bfr[fn >> 1][(fn & 1) * 2]);
            }
        }
        __syncthreads();
    }

    // ---- epilogue A: stage raw accumulators to smem as fp16 ----
    __half* gbuf = (__half*)sm;
    int gid = lane >> 2;
    int tig = lane & 3;
#pragma unroll
    for (int fm = 0; fm < 4; ++fm) {
        int r0 = wm + fm * 16 + gid;
#pragma unroll
        for (int fn = 0; fn < 4; ++fn) {
            int col = wn + fn * 8 + tig * 2;
            *(__half2*)&gbuf[r0 * GST + col] =
                __floats2half2_rn(acc[fm][fn][0], acc[fm][fn][1]);
            *(__half2*)&gbuf[(r0 + 8) * GST + col] =
                __floats2half2_rn(acc[fm][fn][2], acc[fm][fn][3]);
        }
    }
    __syncthreads();

    // ---- epilogue B: cell update, coalesced global I/O ----
    int qloc = tid & 31;
    int q_glob = (n0 >> 2) + qloc;
    float4 bv = *(const float4*)(bperm + n0 + qloc * 4);   // (bi,bf,bg,bo)
#pragma unroll
    for (int rr = tid >> 5; rr < 128; rr += 8) {
        int row = m0 + rr;
        if (row >= M) continue;
        uint2 raw = *(uint2*)&gbuf[rr * GST + qloc * 4];
        __half2 p0 = *(__half2*)&raw.x;   // (i, f)
        __half2 p1 = *(__half2*)&raw.y;   // (g, o)
        float2 v0 = __half22float2(p0);
        float2 v1 = __half22float2(p1);
        float gi = sigf(v0.x + bv.x);
        float gf = sigf(v0.y + bv.y);
        float gg = tanh_fast(v1.x + bv.z);
        float go = sigf(v1.y + bv.w);
        size_t ci = (size_t)row * DIM + q_glob;
        float cn = gf * c[ci] + gi * gg;
        float hn = go * tanh_fast(cn);
        c[ci] = cn;
        hh_out[ci] = __float2half_rn(hn);
        if (write_h) hfp[ci] = hn;
    }
}

// ------------------------------ GCN fp32 GEMM ------------------------------
#define BM 128
#define BN 128
#define BK 16
#define TM 8
#define TN 8

__global__ __launch_bounds__(256) void gemm_kn_k(
    const float* __restrict__ A, const float* __restrict__ B,
    float* __restrict__ C, int M) {
    __shared__ float As[BK][BM];
    __shared__ float Bs[BK][BN];
    int tid = threadIdx.x;
    int m0 = blockIdx.x * BM;
    int ty = tid >> 4;
    int tx = tid & 15;
    float acc[TM][TN] = {};

    for (int kc = 0; kc < 8; ++kc) {
        int kbase = kc * BK;
#pragma unroll
        for (int p = 0; p < 2; ++p) {
            int ar = (tid >> 2) + p * 64;
            int ac = (tid & 3) * 4;
            int gm = m0 + ar;
            float4 v = make_float4(0.f, 0.f, 0.f, 0.f);
            if (gm < M) v = *(const float4*)(A + (size_t)gm * DIM + kbase + ac);
            As[ac + 0][ar] = v.x; As[ac + 1][ar] = v.y;
            As[ac + 2][ar] = v.z; As[ac + 3][ar] = v.w;
        }
#pragma unroll
        for (int p = 0; p < 2; ++p) {
            int k = (tid >> 5) + p * 8;
            int c4 = (tid & 31) * 4;
            float4 v = *(const float4*)(B + (size_t)(kbase + k) * DIM + c4);
            *(float4*)&Bs[k][c4] = v;
        }
        __syncthreads();
#pragma unroll
        for (int k = 0; k < BK; ++k) {
            float a[TM], b[TN];
            *(float4*)&a[0] = *(const float4*)&As[k][ty * TM];
            *(float4*)&a[4] = *(const float4*)&As[k][ty * TM + 4];
            *(float4*)&b[0] = *(const float4*)&Bs[k][tx * TN];
            *(float4*)&b[4] = *(const float4*)&Bs[k][tx * TN + 4];
#pragma unroll
            for (int i = 0; i < TM; ++i)
#pragma unroll
                for (int j = 0; j < TN; ++j) acc[i][j] += a[i] * b[j];
        }
        __syncthreads();
    }

#pragma unroll
    for (int i = 0; i < TM; ++i) {
        int m = m0 + ty * TM + i;
        if (m >= M) continue;
        float* crow = C + (size_t)m * DIM + tx * TN;
#pragma unroll
        for (int j4 = 0; j4 < TN; j4 += 4) {
            float4 o;
            o.x = acc[i][j4 + 0]; o.y = acc[i][j4 + 1];
            o.z = acc[i][j4 + 2]; o.w = acc[i][j4 + 3];
            *(float4*)(crow + j4) = o;
        }
    }
}

// ------------------------------ GCN scatter (vector RED) -------------------
__global__ void scatter_add_k(const float* __restrict__ feat,
                              const void* __restrict__ edges_raw, long long E,
                              const int* __restrict__ eflag, int Nn,
                              float* __restrict__ out) {
    long long gt = (long long)blockIdx.x * blockDim.x + threadIdx.x;
    long long e = gt >> 5;
    if (e >= E) return;
    int lane = (int)(gt & 31);
    long long s, d;
    if (*eflag) {
        const long long* ed = (const long long*)edges_raw;
        s = ed[e];
        d = ed[E + e];
    } else {
        const int* ed = (const int*)edges_raw;
        s = ed[e];
        d = ed[E + e];
    }
    if (s < 0 || s >= Nn || d < 0 || d >= Nn) return;
    float4 v = *(const float4*)(feat + s * DIM + lane * 4);
    red_add_v4(out + d * DIM + lane * 4, v);
}

// ------------------------------ host launcher ------------------------------
extern "C" void kernel_launch(void* const* d_in, const int* in_sizes, int n_in,
                              void* d_out, int out_size) {
    const float* input_aux = (const float*)d_in[0];
    const void*  edges     = d_in[1];
    const float* W_ih      = (const float*)d_in[2];
    const float* W_hh      = (const float*)d_in[3];
    const float* b_ih      = (const float*)d_in[4];
    const float* b_hh      = (const float*)d_in[5];
    const float* W1        = (const float*)d_in[6];
    const float* b1        = (const float*)d_in[7];
    const float* W2        = (const float*)d_in[8];
    const float* b2        = (const float*)d_in[9];
    float* out = (float*)d_out;

    int Nn  = out_size / DIM;
    int seq = in_sizes[0] / (Nn * DIM);
    long long E = (long long)in_sizes[1] / 2;

    float *h, *c, *t1, *t2, *bperm;
    __half *xh, *hh0, *wc;
    int* eflag;
    cudaGetSymbolAddress((void**)&h,     g_h);
    cudaGetSymbolAddress((void**)&c,     g_c);
    cudaGetSymbolAddress((void**)&t1,    g_t1);
    cudaGetSymbolAddress((void**)&t2,    g_t2);
    cudaGetSymbolAddress((void**)&bperm, g_bperm);
    cudaGetSymbolAddress((void**)&eflag, g_eflag);
    cudaGetSymbolAddress((void**)&xh,    g_xh);
    cudaGetSymbolAddress((void**)&hh0,   g_hh);
    cudaGetSymbolAddress((void**)&wc,    g_wc);

    size_t hstride = (size_t)MAXN * DIM;
    __half* hh[2] = {hh0, hh0 + hstride};

    int nd = Nn * DIM;
    int eb = 256;

    detect_edge_dtype_k<<<1, 256>>>((const int*)edges, 2 * E, eflag);
    bias_perm_k<<<1, NG>>>(b_ih, b_hh, bperm);
    fill_zero_k<<<(nd + eb - 1) / eb, eb>>>(c, nd);
    fill_zero_k<<<(nd / 2 + eb - 1) / eb, eb>>>((float*)hh[0], nd / 2);

    int xn4 = (seq * nd) / 4;
    cvt_half_k<<<(xn4 + eb - 1) / eb, eb>>>(input_aux, xh, xn4);
    build_wcat_k<<<(NG * 256 + eb - 1) / eb, eb>>>(W_ih, W_hh, wc);

    dim3 ggate((Nn + 127) / 128, 4);
    for (int t = 0; t < seq; ++t) {
        const __half* xt = xh + (size_t)t * nd;
        int rb = t & 1, wb = (t + 1) & 1;
        gemm_lstm_fused<<<ggate, 256>>>(
            xt, hh[rb], wc, bperm, c, h, hh[wb], Nn,
            (t == seq - 1) ? 1 : 0);
    }

    dim3 ggcn((Nn + BM - 1) / BM, 1);
    long long sth = E * 32;
    unsigned sblocks = (unsigned)((sth + eb - 1) / eb);

    gemm_kn_k<<<ggcn, 256>>>(h, W1, t1, Nn);
    fill_zero_k<<<(nd + eb - 1) / eb, eb>>>(t2, nd);
    scatter_add_k<<<sblocks, eb>>>(t1, edges, E, eflag, Nn, t2);
    relu_bias_k<<<(nd + eb - 1) / eb, eb>>>(t2, b1, t1, nd);

    gemm_kn_k<<<ggcn, 256>>>(t1, W2, t2, Nn);
    fill_bias_k<<<(nd + eb - 1) / eb, eb>>>(out, b2, nd);
    scatter_add_k<<<sblocks, eb>>>(t2, edges, E, eflag, Nn, out);
}

// round 14
// speedup vs baseline: 1.0464x; 1.0464x over previous
#include <cuda_runtime.h>
#include <cuda_bf16.h>
#include <cuda_fp16.h>
#include <math.h>
#include <stdint.h>

// ---------------------------------------------------------------------------
// lstm_gcn round 14: R12 base (single-pass fp16 gate GEMM, MUFU.TANH cell,
// red.v4 scatter) + GCN GEMMs moved to tensor pipe via 3-pass split-fp16
// (hi*whi + hi*wlo + lo*whi, fp32 acc, error ~1e-6). fp32 h eliminated:
// cell emits h-hi (=hh) every step and h-lo on the last step.
// ---------------------------------------------------------------------------

#define MAXN   50000
#define MAXSEQ 16
#define DIM    128
#define NG     512

__device__ float  g_c[MAXN * DIM];
__device__ __half g_gates[MAXN * NG];
__device__ float  g_t1[MAXN * DIM];
__device__ float  g_t2[MAXN * DIM];
__device__ float  g_bsum[NG];
__device__ int    g_eflag;

__device__ __half g_xh[MAXSEQ * MAXN * DIM];   // x in fp16
__device__ __half g_hh[MAXN * DIM];            // h fp16 (hi)
__device__ __half g_hlo[MAXN * DIM];           // h fp16 residual (last step)
__device__ __half g_wc[NG * 256];              // [512][256] = [W_ih | W_hh] fp16
__device__ __half g_w1thi[DIM * DIM];          // W1^T hi  [n][k]
__device__ __half g_w1tlo[DIM * DIM];          // W1^T lo
__device__ __half g_w2thi[DIM * DIM];          // W2^T hi
__device__ __half g_w2tlo[DIM * DIM];          // W2^T lo

// ------------------------------ helpers ------------------------------------
__device__ __forceinline__ uint32_t smem_u32(const void* p) {
    uint32_t a;
    asm("{ .reg .u64 t; cvta.to.shared.u64 t, %1; cvt.u32.u64 %0, t; }"
        : "=r"(a) : "l"(p));
    return a;
}

__device__ __forceinline__ void ldsm4(uint32_t* r, uint32_t addr) {
    asm volatile("ldmatrix.sync.aligned.m8n8.x4.shared.b16 {%0,%1,%2,%3}, [%4];"
                 : "=r"(r[0]), "=r"(r[1]), "=r"(r[2]), "=r"(r[3]) : "r"(addr));
}

__device__ __forceinline__ void mma_f16(float* d, const uint32_t* a,
                                        const uint32_t* b) {
    asm volatile(
        "mma.sync.aligned.m16n8k16.row.col.f32.f16.f16.f32 "
        "{%0,%1,%2,%3}, {%4,%5,%6,%7}, {%8,%9}, {%0,%1,%2,%3};"
        : "+f"(d[0]), "+f"(d[1]), "+f"(d[2]), "+f"(d[3])
        : "r"(a[0]), "r"(a[1]), "r"(a[2]), "r"(a[3]), "r"(b[0]), "r"(b[1]));
}

__device__ __forceinline__ void cp_async16(uint32_t dst, const void* src) {
    asm volatile("cp.async.cg.shared.global [%0], [%1], 16;"
                 :: "r"(dst), "l"(src));
}
__device__ __forceinline__ void cp_commit() {
    asm volatile("cp.async.commit_group;");
}
__device__ __forceinline__ void cp_wait1() {
    asm volatile("cp.async.wait_group 1;");
}
__device__ __forceinline__ void cp_wait0() {
    asm volatile("cp.async.wait_group 0;");
}

// HW tanh (MUFU.TANH), rel err ~2^-11
__device__ __forceinline__ float tanh_fast(float x) {
    float y;
    asm("tanh.approx.f32 %0, %1;" : "=f"(y) : "f"(x));
    return y;
}
__device__ __forceinline__ float sigf(float x) {
    return fmaf(tanh_fast(0.5f * x), 0.5f, 0.5f);
}

// vector reduction (sm_90+): 4 floats in one op
__device__ __forceinline__ void red_add_v4(float* addr, float4 v) {
    asm volatile("red.global.add.v4.f32 [%0], {%1, %2, %3, %4};"
                 :: "l"(addr), "f"(v.x), "f"(v.y), "f"(v.z), "f"(v.w)
                 : "memory");
}

// ------------------------------ edge dtype detect --------------------------
__global__ void detect_edge_dtype_k(const int* __restrict__ e32, long long n32,
                                    int* __restrict__ flag) {
    __shared__ int nz;
    if (threadIdx.x == 0) nz = 0;
    __syncthreads();
    for (long long i = threadIdx.x; i < 4096; i += blockDim.x) {
        long long idx = 2 * i + 1;
        if (idx < n32 && e32[idx] != 0) atomicOr(&nz, 1);
    }
    __syncthreads();
    if (threadIdx.x == 0) *flag = (nz == 0) ? 1 : 0;
}

// ------------------------------ small kernels ------------------------------
__global__ void fill_zero_k(float* __restrict__ p, int n) {
    int i = blockIdx.x * blockDim.x + threadIdx.x;
    if (i < n) p[i] = 0.0f;
}

__global__ void bias_sum_k(const float* __restrict__ a, const float* __restrict__ b,
                           float* __restrict__ o) {
    int i = threadIdx.x;
    o[i] = a[i] + b[i];
}

__global__ void fill_bias_k(float* __restrict__ out, const float* __restrict__ b, int total) {
    int i = blockIdx.x * blockDim.x + threadIdx.x;
    if (i < total) out[i] = b[i & (DIM - 1)];
}

// relu(in + bias), emit fp16 hi/lo split (for split-fp16 GEMM input)
__global__ void relu_bias_split_k(const float* __restrict__ in,
                                  const float* __restrict__ b,
                                  __half* __restrict__ hi,
                                  __half* __restrict__ lo, int n4) {
    int i = blockIdx.x * blockDim.x + threadIdx.x;
    if (i >= n4) return;
    float4 v = ((const float4*)in)[i];
    const float* bb = b + ((i * 4) & (DIM - 1));
    float4 r;
    r.x = fmaxf(v.x + bb[0], 0.0f);
    r.y = fmaxf(v.y + bb[1], 0.0f);
    r.z = fmaxf(v.z + bb[2], 0.0f);
    r.w = fmaxf(v.w + bb[3], 0.0f);
    __half2 h0 = __floats2half2_rn(r.x, r.y);
    __half2 h1 = __floats2half2_rn(r.z, r.w);
    float2 f0 = __half22float2(h0), f1 = __half22float2(h1);
    __half2* hp = (__half2*)(hi + (size_t)i * 4);
    __half2* lp = (__half2*)(lo + (size_t)i * 4);
    hp[0] = h0; hp[1] = h1;
    lp[0] = __floats2half2_rn(r.x - f0.x, r.y - f0.y);
    lp[1] = __floats2half2_rn(r.z - f1.x, r.w - f1.y);
}

// fp32 -> fp16 convert (vectorized x4)
__global__ void cvt_half_k(const float* __restrict__ src,
                           __half* __restrict__ dst, int n4) {
    int i = blockIdx.x * blockDim.x + threadIdx.x;
    if (i >= n4) return;
    float4 v = ((const float4*)src)[i];
    __half2* dp = (__half2*)(dst + (size_t)i * 4);
    dp[0] = __floats2half2_rn(v.x, v.y);
    dp[1] = __floats2half2_rn(v.z, v.w);
}

// Wcat[512][256] = [W_ih | W_hh] in fp16
__global__ void build_wcat_k(const float* __restrict__ wih, const float* __restrict__ whh,
                             __half* __restrict__ wc) {
    int idx = blockIdx.x * blockDim.x + threadIdx.x;
    if (idx >= NG * 256) return;
    int n = idx >> 8, k = idx & 255;
    float v = (k < 128) ? wih[n * 128 + k] : whh[n * 128 + (k - 128)];
    wc[idx] = __float2half_rn(v);
}

// W^T hi/lo: wt[n][k] = W[k][n] split into fp16 hi + residual
__global__ void build_wt_k(const float* __restrict__ w,
                           __half* __restrict__ hi, __half* __restrict__ lo) {
    int idx = blockIdx.x * blockDim.x + threadIdx.x;
    if (idx >= DIM * DIM) return;
    int n = idx >> 7, k = idx & 127;
    float v = w[k * DIM + n];
    __half h = __float2half_rn(v);
    hi[idx] = h;
    lo[idx] = __float2half_rn(v - __half2float(h));
}

// ------------------------------ LSTM cell ----------------------------------
__global__ void lstm_cell_k(const __half* __restrict__ gates,
                            float* __restrict__ c,
                            __half* __restrict__ hh,
                            __half* __restrict__ hlo, int Nn, int write_lo) {
    int idx = blockIdx.x * blockDim.x + threadIdx.x;
    if (idx >= Nn * 32) return;
    int n = idx >> 5;
    int q = (idx & 31) * 4;
    const __half2* gr = (const __half2*)(gates + (size_t)n * NG + q);
    float2 i01 = __half22float2(gr[0]);
    float2 i23 = __half22float2(gr[1]);
    float2 f01 = __half22float2(gr[64]);   // +128 halves
    float2 f23 = __half22float2(gr[65]);
    float2 g01 = __half22float2(gr[128]);  // +256
    float2 g23 = __half22float2(gr[129]);
    float2 o01 = __half22float2(gr[192]);  // +384
    float2 o23 = __half22float2(gr[193]);
    float* cp = c + (size_t)n * DIM + q;
    float4 cv = *(const float4*)cp;
    float4 cn, hn;
    cn.x = sigf(f01.x) * cv.x + sigf(i01.x) * tanh_fast(g01.x);
    cn.y = sigf(f01.y) * cv.y + sigf(i01.y) * tanh_fast(g01.y);
    cn.z = sigf(f23.x) * cv.z + sigf(i23.x) * tanh_fast(g23.x);
    cn.w = sigf(f23.y) * cv.w + sigf(i23.y) * tanh_fast(g23.y);
    hn.x = sigf(o01.x) * tanh_fast(cn.x);
    hn.y = sigf(o01.y) * tanh_fast(cn.y);
    hn.z = sigf(o23.x) * tanh_fast(cn.z);
    hn.w = sigf(o23.y) * tanh_fast(cn.w);
    *(float4*)cp = cn;
    __half2 h01 = __floats2half2_rn(hn.x, hn.y);
    __half2 h23 = __floats2half2_rn(hn.z, hn.w);
    __half2* hhp = (__half2*)(hh + (size_t)n * DIM + q);
    hhp[0] = h01;
    hhp[1] = h23;
    if (write_lo) {
        float2 f0 = __half22float2(h01), f1 = __half22float2(h23);
        __half2* lp = (__half2*)(hlo + (size_t)n * DIM + q);
        lp[0] = __floats2half2_rn(hn.x - f0.x, hn.y - f0.y);
        lp[1] = __floats2half2_rn(hn.z - f1.x, hn.w - f1.y);
    }
}

// ---------------------------------------------------------------------------
// LSTM gate GEMM via mma.sync fp16, SINGLE pass.
// Block tile 128x128, 8 warps (2x4) of 64x32 warp tiles, BK=32, double-
// buffered cp.async. K loop: 8 iterations over K=256 ([x | h]).
// ---------------------------------------------------------------------------
#define ROWB 80     // bytes per smem row (32 fp16 data + pad)
#define ATILE 10240 // 128 * 80
#define NITER 8

__global__ __launch_bounds__(256, 2) void gemm_lstm_mma(
    const __half* __restrict__ xh, const __half* __restrict__ hh,
    const __half* __restrict__ wc,
    const float* __restrict__ bias,
    __half* __restrict__ C, int M) {
    __shared__ __align__(128) char sm[4 * ATILE];  // A0 A1 B0 B1

    int tid  = threadIdx.x;
    int wid  = tid >> 5;
    int lane = tid & 31;
    int m0 = blockIdx.x * 128;
    int n0 = blockIdx.y * 128;

    uint32_t sbase = smem_u32(sm);
    int wm = (wid >> 2) * 64;
    int wn = (wid & 3) * 32;

    int a_row  = (lane & 7) + ((lane >> 3) & 1) * 8;
    int a_kch  = lane >> 4;
    int b_row  = (lane & 7) + (lane >> 4) * 8;
    int b_kch  = (lane >> 3) & 1;

    int r0c = tid >> 2;
    int ch  = (tid & 3);

    float acc[4][4][4];
#pragma unroll
    for (int i = 0; i < 4; ++i)
#pragma unroll
        for (int j = 0; j < 4; ++j)
#pragma unroll
            for (int q = 0; q < 4; ++q) acc[i][j][q] = 0.0f;

    auto issue = [&](int i, int b) {
        int kc = i & 7;             // 0..7 over K=256
        const __half* Ap = (kc < 4) ? xh : hh;
        int ka = (kc & 3) * 32;
        int kb = kc * 32;

        uint32_t dA = sbase + b * ATILE;
        uint32_t dB = sbase + 2 * ATILE + b * ATILE;
#pragma unroll
        for (int it = 0; it < 2; ++it) {
            int r = r0c + it * 64;
            int gm = m0 + r;
            const __half* src =
                Ap + (size_t)(gm < M ? gm : 0) * DIM + ka + ch * 8;
            cp_async16(dA + r * ROWB + ch * 16, src);
        }
#pragma unroll
        for (int it = 0; it < 2; ++it) {
            int r = r0c + it * 64;
            const __half* src = wc + (size_t)(n0 + r) * 256 + kb + ch * 8;
            cp_async16(dB + r * ROWB + ch * 16, src);
        }
        cp_commit();
    };

    issue(0, 0);

    for (int i = 0; i < NITER; ++i) {
        if (i + 1 < NITER) issue(i + 1, (i + 1) & 1);
        if (i + 1 < NITER) cp_wait1(); else cp_wait0();
        __syncthreads();

        int b = i & 1;
        uint32_t sA = sbase + b * ATILE;
        uint32_t sB = sbase + 2 * ATILE + b * ATILE;

#pragma unroll
        for (int k16 = 0; k16 < 2; ++k16) {
            uint32_t afr[4][4];
            uint32_t bfr[2][4];
#pragma unroll
            for (int fm = 0; fm < 4; ++fm) {
                uint32_t addr = sA + (wm + fm * 16 + a_row) * ROWB
                              + (k16 * 2 + a_kch) * 16;
                ldsm4(afr[fm], addr);
            }
#pragma unroll
            for (int fn2 = 0; fn2 < 2; ++fn2) {
                uint32_t addr = sB + (wn + fn2 * 16 + b_row) * ROWB
                              + (k16 * 2 + b_kch) * 16;
                ldsm4(bfr[fn2], addr);
            }
#pragma unroll
            for (int fm = 0; fm < 4; ++fm) {
#pragma unroll
                for (int fn = 0; fn < 4; ++fn)
                    mma_f16(acc[fm][fn], afr[fm], &bfr[fn >> 1][(fn & 1) * 2]);
            }
        }
        __syncthreads();
    }

    // ---- epilogue: add bias, store fp16 gates ----
    int gid = lane >> 2;
    int tig = lane & 3;
    float2 bfr2[4];
#pragma unroll
    for (int fn = 0; fn < 4; ++fn) {
        int n = n0 + wn + fn * 8 + tig * 2;
        bfr2[fn] = *(const float2*)(bias + n);
    }
#pragma unroll
    for (int fm = 0; fm < 4; ++fm) {
        int mlo = m0 + wm + fm * 16 + gid;
        int mhi = mlo + 8;
#pragma unroll
        for (int fn = 0; fn < 4; ++fn) {
            int n = n0 + wn + fn * 8 + tig * 2;
            if (mlo < M) {
                __half2 o = __floats2half2_rn(acc[fm][fn][0] + bfr2[fn].x,
                                              acc[fm][fn][1] + bfr2[fn].y);
                *(__half2*)(C + (size_t)mlo * NG + n) = o;
            }
            if (mhi < M) {
                __half2 o = __floats2half2_rn(acc[fm][fn][2] + bfr2[fn].x,
                                              acc[fm][fn][3] + bfr2[fn].y);
                *(__half2*)(C + (size_t)mhi * NG + n) = o;
            }
        }
    }
}

// ---------------------------------------------------------------------------
// GCN GEMM: C[M,128] = A[M,128] @ W[K=128,N=128] via 3-pass split-fp16.
// A given as (ahi, alo); W as transposed fp16 (whi, wlo) [n][k].
// Passes: ahi*whi + ahi*wlo + alo*whi (fp32 acc; fp16 products exact in
// fp32 -> error ~1e-6). 12 k-iterations (3 passes x K=128 / 32).
// ---------------------------------------------------------------------------
#define GNITER 12

__global__ __launch_bounds__(256, 2) void gemm_gcn_split(
    const __half* __restrict__ ahi, const __half* __restrict__ alo,
    const __half* __restrict__ whi, const __half* __restrict__ wlo,
    float* __restrict__ C, int M) {
    __shared__ __align__(128) char sm[4 * ATILE];  // A0 A1 B0 B1

    int tid  = threadIdx.x;
    int wid  = tid >> 5;
    int lane = tid & 31;
    int m0 = blockIdx.x * 128;

    uint32_t sbase = smem_u32(sm);
    int wm = (wid >> 2) * 64;
    int wn = (wid & 3) * 32;

    int a_row  = (lane & 7) + ((lane >> 3) & 1) * 8;
    int a_kch  = lane >> 4;
    int b_row  = (lane & 7) + (lane >> 4) * 8;
    int b_kch  = (lane >> 3) & 1;

    int r0c = tid >> 2;
    int ch  = (tid & 3);

    float acc[4][4][4];
#pragma unroll
    for (int i = 0; i < 4; ++i)
#pragma unroll
        for (int j = 0; j < 4; ++j)
#pragma unroll
            for (int q = 0; q < 4; ++q) acc[i][j][q] = 0.0f;

    auto issue = [&](int i, int b) {
        int pass = i >> 2;          // 0: hi*whi, 1: hi*wlo, 2: lo*whi
        int kc   = i & 3;           // K chunk within 128
        const __half* Ap = (pass == 2) ? alo : ahi;
        const __half* Wp = (pass == 1) ? wlo : whi;
        int k0 = kc * 32;

        uint32_t dA = sbase + b * ATILE;
        uint32_t dB = sbase + 2 * ATILE + b * ATILE;
#pragma unroll
        for (int it = 0; it < 2; ++it) {
            int r = r0c + it * 64;
            int gm = m0 + r;
            const __half* src =
                Ap + (size_t)(gm < M ? gm : 0) * DIM + k0 + ch * 8;
            cp_async16(dA + r * ROWB + ch * 16, src);
        }
#pragma unroll
        for (int it = 0; it < 2; ++it) {
            int r = r0c + it * 64;
            const __half* src = Wp + (size_t)r * DIM + k0 + ch * 8;
            cp_async16(dB + r * ROWB + ch * 16, src);
        }
        cp_commit();
    };

    issue(0, 0);

    for (int i = 0; i < GNITER; ++i) {
        if (i + 1 < GNITER) issue(i + 1, (i + 1) & 1);
        if (i + 1 < GNITER) cp_wait1(); else cp_wait0();
        __syncthreads();

        int b = i & 1;
        uint32_t sA = sbase + b * ATILE;
        uint32_t sB = sbase + 2 * ATILE + b * ATILE;

#pragma unroll
        for (int k16 = 0; k16 < 2; ++k16) {
            uint32_t afr[4][4];
            uint32_t bfr[2][4];
#pragma unroll
            for (int fm = 0; fm < 4; ++fm) {
                uint32_t addr = sA + (wm + fm * 16 + a_row) * ROWB
                              + (k16 * 2 + a_kch) * 16;
                ldsm4(afr[fm], addr);
            }
#pragma unroll
            for (int fn2 = 0; fn2 < 2; ++fn2) {
                uint32_t addr = sB + (wn + fn2 * 16 + b_row) * ROWB
                              + (k16 * 2 + b_kch) * 16;
                ldsm4(bfr[fn2], addr);
            }
#pragma unroll
            for (int fm = 0; fm < 4; ++fm) {
#pragma unroll
                for (int fn = 0; fn < 4; ++fn)
                    mma_f16(acc[fm][fn], afr[fm], &bfr[fn >> 1][(fn & 1) * 2]);
            }
        }
        __syncthreads();
    }

    // ---- epilogue: store fp32 ----
    int gid = lane >> 2;
    int tig = lane & 3;
#pragma unroll
    for (int fm = 0; fm < 4; ++fm) {
        int mlo = m0 + wm + fm * 16 + gid;
        int mhi = mlo + 8;
#pragma unroll
        for (int fn = 0; fn < 4; ++fn) {
            int n = wn + fn * 8 + tig * 2;
            if (mlo < M)
                *(float2*)(C + (size_t)mlo * DIM + n) =
                    make_float2(acc[fm][fn][0], acc[fm][fn][1]);
            if (mhi < M)
                *(float2*)(C + (size_t)mhi * DIM + n) =
                    make_float2(acc[fm][fn][2], acc[fm][fn][3]);
        }
    }
}

// ------------------------------ GCN scatter (vector RED) -------------------
__global__ void scatter_add_k(const float* __restrict__ feat,
                              const void* __restrict__ edges_raw, long long E,
                              const int* __restrict__ eflag, int Nn,
                              float* __restrict__ out) {
    long long gt = (long long)blockIdx.x * blockDim.x + threadIdx.x;
    long long e = gt >> 5;
    if (e >= E) return;
    int lane = (int)(gt & 31);
    long long s, d;
    if (*eflag) {
        const long long* ed = (const long long*)edges_raw;
        s = ed[e];
        d = ed[E + e];
    } else {
        const int* ed = (const int*)edges_raw;
        s = ed[e];
        d = ed[E + e];
    }
    if (s < 0 || s >= Nn || d < 0 || d >= Nn) return;
    float4 v = *(const float4*)(feat + s * DIM + lane * 4);
    red_add_v4(out + d * DIM + lane * 4, v);
}

// ------------------------------ host launcher ------------------------------
extern "C" void kernel_launch(void* const* d_in, const int* in_sizes, int n_in,
                              void* d_out, int out_size) {
    const float* input_aux = (const float*)d_in[0];
    const void*  edges     = d_in[1];
    const float* W_ih      = (const float*)d_in[2];
    const float* W_hh      = (const float*)d_in[3];
    const float* b_ih      = (const float*)d_in[4];
    const float* b_hh      = (const float*)d_in[5];
    const float* W1        = (const float*)d_in[6];
    const float* b1        = (const float*)d_in[7];
    const float* W2        = (const float*)d_in[8];
    const float* b2        = (const float*)d_in[9];
    float* out = (float*)d_out;

    int Nn  = out_size / DIM;
    int seq = in_sizes[0] / (Nn * DIM);
    long long E = (long long)in_sizes[1] / 2;

    float *c, *t1, *t2, *bsum;
    __half *gates, *xh, *hh, *hlo, *wc;
    __half *w1thi, *w1tlo, *w2thi, *w2tlo;
    int* eflag;
    cudaGetSymbolAddress((void**)&c,     g_c);
    cudaGetSymbolAddress((void**)&gates, g_gates);
    cudaGetSymbolAddress((void**)&t1,    g_t1);
    cudaGetSymbolAddress((void**)&t2,    g_t2);
    cudaGetSymbolAddress((void**)&bsum,  g_bsum);
    cudaGetSymbolAddress((void**)&eflag, g_eflag);
    cudaGetSymbolAddress((void**)&xh,    g_xh);
    cudaGetSymbolAddress((void**)&hh,    g_hh);
    cudaGetSymbolAddress((void**)&hlo,   g_hlo);
    cudaGetSymbolAddress((void**)&wc,    g_wc);
    cudaGetSymbolAddress((void**)&w1thi, g_w1thi);
    cudaGetSymbolAddress((void**)&w1tlo, g_w1tlo);
    cudaGetSymbolAddress((void**)&w2thi, g_w2thi);
    cudaGetSymbolAddress((void**)&w2tlo, g_w2tlo);

    int nd = Nn * DIM;
    int eb = 256;

    detect_edge_dtype_k<<<1, 256>>>((const int*)edges, 2 * E, eflag);
    bias_sum_k<<<1, NG>>>(b_ih, b_hh, bsum);
    fill_zero_k<<<(nd + eb - 1) / eb, eb>>>(c, nd);
    fill_zero_k<<<(nd / 2 + eb - 1) / eb, eb>>>((float*)hh, nd / 2);

    int xn4 = (seq * nd) / 4;
    cvt_half_k<<<(xn4 + eb - 1) / eb, eb>>>(input_aux, xh, xn4);
    build_wcat_k<<<(NG * 256 + eb - 1) / eb, eb>>>(W_ih, W_hh, wc);
    build_wt_k<<<(DIM * DIM + eb - 1) / eb, eb>>>(W1, w1thi, w1tlo);
    build_wt_k<<<(DIM * DIM + eb - 1) / eb, eb>>>(W2, w2thi, w2tlo);

    dim3 ggate((Nn + 127) / 128, 4);
    int cell_threads = Nn * 32;
    for (int t = 0; t < seq; ++t) {
        const __half* xt = xh + (size_t)t * nd;
        gemm_lstm_mma<<<ggate, 256>>>(xt, hh, wc, bsum, gates, Nn);
        lstm_cell_k<<<(cell_threads + eb - 1) / eb, eb>>>(
            gates, c, hh, hlo, Nn, (t == seq - 1) ? 1 : 0);
    }

    dim3 ggcn((Nn + 127) / 128, 1);
    long long sth = E * 32;
    unsigned sblocks = (unsigned)((sth + eb - 1) / eb);

    // GCN layer 1: t1 = h @ W1 (split fp16); t2 = scatter(t1);
    // hh/hlo then reused for relu-split output.
    gemm_gcn_split<<<ggcn, 256>>>(hh, hlo, w1thi, w1tlo, t1, Nn);
    fill_zero_k<<<(nd + eb - 1) / eb, eb>>>(t2, nd);
    scatter_add_k<<<sblocks, eb>>>(t1, edges, E, eflag, Nn, t2);
    relu_bias_split_k<<<(nd / 4 + eb - 1) / eb, eb>>>(t2, b1, hh, hlo, nd / 4);

    // GCN layer 2: t2 = relu_out @ W2 (split fp16); out = b2 + scatter(t2)
    gemm_gcn_split<<<ggcn, 256>>>(hh, hlo, w2thi, w2tlo, t2, Nn);
    fill_bias_k<<<(nd + eb - 1) / eb, eb>>>(out, b2, nd);
    scatter_add_k<<<sblocks, eb>>>(t2, edges, E, eflag, Nn, out);
}

// round 15
// speedup vs baseline: 1.1804x; 1.1281x over previous
#include <cuda_runtime.h>
#include <cuda_bf16.h>
#include <cuda_fp16.h>
#include <math.h>
#include <stdint.h>

// ---------------------------------------------------------------------------
// lstm_gcn round 15: R14 base (fp16 single-pass gate GEMM, MUFU.TANH cell,
// split-fp16 GCN GEMMs) + CSR gather-sum GCN aggregation (replaces atomic
// scatter: kills ~820MB/layer of RED traffic; exact per-node fp32 sums).
// ---------------------------------------------------------------------------

#define MAXN   50000
#define MAXE   1600000
#define MAXSEQ 16
#define DIM    128
#define NG     512

__device__ float  g_c[MAXN * DIM];
__device__ __half g_gates[MAXN * NG];
__device__ float  g_t1[MAXN * DIM];
__device__ float  g_t2[MAXN * DIM];
__device__ float  g_bsum[NG];
__device__ int    g_eflag;

__device__ int    g_deg[MAXN];
__device__ int    g_off[MAXN + 1];
__device__ int    g_cur[MAXN];
__device__ int    g_csr_src[MAXE];

__device__ __half g_xh[MAXSEQ * MAXN * DIM];   // x in fp16
__device__ __half g_hh[MAXN * DIM];            // h fp16 (hi)
__device__ __half g_hlo[MAXN * DIM];           // h fp16 residual (last step)
__device__ __half g_wc[NG * 256];              // [512][256] = [W_ih | W_hh] fp16
__device__ __half g_w1thi[DIM * DIM];          // W1^T hi  [n][k]
__device__ __half g_w1tlo[DIM * DIM];          // W1^T lo
__device__ __half g_w2thi[DIM * DIM];          // W2^T hi
__device__ __half g_w2tlo[DIM * DIM];          // W2^T lo

// ------------------------------ helpers ------------------------------------
__device__ __forceinline__ uint32_t smem_u32(const void* p) {
    uint32_t a;
    asm("{ .reg .u64 t; cvta.to.shared.u64 t, %1; cvt.u32.u64 %0, t; }"
        : "=r"(a) : "l"(p));
    return a;
}

__device__ __forceinline__ void ldsm4(uint32_t* r, uint32_t addr) {
    asm volatile("ldmatrix.sync.aligned.m8n8.x4.shared.b16 {%0,%1,%2,%3}, [%4];"
                 : "=r"(r[0]), "=r"(r[1]), "=r"(r[2]), "=r"(r[3]) : "r"(addr));
}

__device__ __forceinline__ void mma_f16(float* d, const uint32_t* a,
                                        const uint32_t* b) {
    asm volatile(
        "mma.sync.aligned.m16n8k16.row.col.f32.f16.f16.f32 "
        "{%0,%1,%2,%3}, {%4,%5,%6,%7}, {%8,%9}, {%0,%1,%2,%3};"
        : "+f"(d[0]), "+f"(d[1]), "+f"(d[2]), "+f"(d[3])
        : "r"(a[0]), "r"(a[1]), "r"(a[2]), "r"(a[3]), "r"(b[0]), "r"(b[1]));
}

__device__ __forceinline__ void cp_async16(uint32_t dst, const void* src) {
    asm volatile("cp.async.cg.shared.global [%0], [%1], 16;"
                 :: "r"(dst), "l"(src));
}
__device__ __forceinline__ void cp_commit() {
    asm volatile("cp.async.commit_group;");
}
__device__ __forceinline__ void cp_wait1() {
    asm volatile("cp.async.wait_group 1;");
}
__device__ __forceinline__ void cp_wait0() {
    asm volatile("cp.async.wait_group 0;");
}

// HW tanh (MUFU.TANH), rel err ~2^-11
__device__ __forceinline__ float tanh_fast(float x) {
    float y;
    asm("tanh.approx.f32 %0, %1;" : "=f"(y) : "f"(x));
    return y;
}
__device__ __forceinline__ float sigf(float x) {
    return fmaf(tanh_fast(0.5f * x), 0.5f, 0.5f);
}

// read edge endpoint pair, dtype-flag dispatched
__device__ __forceinline__ void load_edge(const void* edges_raw, long long E,
                                          int eflag, long long e,
                                          long long& s, long long& d) {
    if (eflag) {
        const long long* ed = (const long long*)edges_raw;
        s = ed[e];
        d = ed[E + e];
    } else {
        const int* ed = (const int*)edges_raw;
        s = ed[e];
        d = ed[E + e];
    }
}

// ------------------------------ edge dtype detect --------------------------
__global__ void detect_edge_dtype_k(const int* __restrict__ e32, long long n32,
                                    int* __restrict__ flag) {
    __shared__ int nz;
    if (threadIdx.x == 0) nz = 0;
    __syncthreads();
    for (long long i = threadIdx.x; i < 4096; i += blockDim.x) {
        long long idx = 2 * i + 1;
        if (idx < n32 && e32[idx] != 0) atomicOr(&nz, 1);
    }
    __syncthreads();
    if (threadIdx.x == 0) *flag = (nz == 0) ? 1 : 0;
}

// ------------------------------ small kernels ------------------------------
__global__ void fill_zero_k(float* __restrict__ p, int n) {
    int i = blockIdx.x * blockDim.x + threadIdx.x;
    if (i < n) p[i] = 0.0f;
}

__global__ void fill_zero_int_k(int* __restrict__ p, int n) {
    int i = blockIdx.x * blockDim.x + threadIdx.x;
    if (i < n) p[i] = 0;
}

__global__ void copy_int_k(const int* __restrict__ a, int* __restrict__ b, int n) {
    int i = blockIdx.x * blockDim.x + threadIdx.x;
    if (i < n) b[i] = a[i];
}

__global__ void bias_sum_k(const float* __restrict__ a, const float* __restrict__ b,
                           float* __restrict__ o) {
    int i = threadIdx.x;
    o[i] = a[i] + b[i];
}

// relu(in + bias), emit fp16 hi/lo split (for split-fp16 GEMM input)
__global__ void relu_bias_split_k(const float* __restrict__ in,
                                  const float* __restrict__ b,
                                  __half* __restrict__ hi,
                                  __half* __restrict__ lo, int n4) {
    int i = blockIdx.x * blockDim.x + threadIdx.x;
    if (i >= n4) return;
    float4 v = ((const float4*)in)[i];
    const float* bb = b + ((i * 4) & (DIM - 1));
    float4 r;
    r.x = fmaxf(v.x + bb[0], 0.0f);
    r.y = fmaxf(v.y + bb[1], 0.0f);
    r.z = fmaxf(v.z + bb[2], 0.0f);
    r.w = fmaxf(v.w + bb[3], 0.0f);
    __half2 h0 = __floats2half2_rn(r.x, r.y);
    __half2 h1 = __floats2half2_rn(r.z, r.w);
    float2 f0 = __half22float2(h0), f1 = __half22float2(h1);
    __half2* hp = (__half2*)(hi + (size_t)i * 4);
    __half2* lp = (__half2*)(lo + (size_t)i * 4);
    hp[0] = h0; hp[1] = h1;
    lp[0] = __floats2half2_rn(r.x - f0.x, r.y - f0.y);
    lp[1] = __floats2half2_rn(r.z - f1.x, r.w - f1.y);
}

// fp32 -> fp16 convert (vectorized x4)
__global__ void cvt_half_k(const float* __restrict__ src,
                           __half* __restrict__ dst, int n4) {
    int i = blockIdx.x * blockDim.x + threadIdx.x;
    if (i >= n4) return;
    float4 v = ((const float4*)src)[i];
    __half2* dp = (__half2*)(dst + (size_t)i * 4);
    dp[0] = __floats2half2_rn(v.x, v.y);
    dp[1] = __floats2half2_rn(v.z, v.w);
}

// Wcat[512][256] = [W_ih | W_hh] in fp16
__global__ void build_wcat_k(const float* __restrict__ wih, const float* __restrict__ whh,
                             __half* __restrict__ wc) {
    int idx = blockIdx.x * blockDim.x + threadIdx.x;
    if (idx >= NG * 256) return;
    int n = idx >> 8, k = idx & 255;
    float v = (k < 128) ? wih[n * 128 + k] : whh[n * 128 + (k - 128)];
    wc[idx] = __float2half_rn(v);
}

// W^T hi/lo: wt[n][k] = W[k][n] split into fp16 hi + residual
__global__ void build_wt_k(const float* __restrict__ w,
                           __half* __restrict__ hi, __half* __restrict__ lo) {
    int idx = blockIdx.x * blockDim.x + threadIdx.x;
    if (idx >= DIM * DIM) return;
    int n = idx >> 7, k = idx & 127;
    float v = w[k * DIM + n];
    __half h = __float2half_rn(v);
    hi[idx] = h;
    lo[idx] = __float2half_rn(v - __half2float(h));
}

// ------------------------------ CSR build ----------------------------------
__global__ void hist_k(const void* __restrict__ edges_raw, long long E,
                       const int* __restrict__ eflag, int Nn,
                       int* __restrict__ deg) {
    long long e = (long long)blockIdx.x * blockDim.x + threadIdx.x;
    if (e >= E) return;
    long long s, d;
    load_edge(edges_raw, E, *eflag, e, s, d);
    if (s < 0 || s >= Nn || d < 0 || d >= Nn) return;
    atomicAdd(&deg[(int)d], 1);
}

// single-block exclusive scan of deg[0..n) -> off[0..n]
__global__ void scan_k(const int* __restrict__ deg, int* __restrict__ off, int n) {
    __shared__ int carry;
    __shared__ int buf[1024];
    if (threadIdx.x == 0) carry = 0;
    __syncthreads();
    for (int base = 0; base < n; base += 1024) {
        int i = base + threadIdx.x;
        int v = (i < n) ? deg[i] : 0;
        buf[threadIdx.x] = v;
        __syncthreads();
#pragma unroll
        for (int s = 1; s < 1024; s <<= 1) {
            int t = (threadIdx.x >= s) ? buf[threadIdx.x - s] : 0;
            __syncthreads();
            buf[threadIdx.x] += t;
            __syncthreads();
        }
        if (i < n) off[i] = carry + buf[threadIdx.x] - v;
        __syncthreads();
        if (threadIdx.x == 1023) carry += buf[1023];
        __syncthreads();
    }
    if (threadIdx.x == 0) off[n] = carry;
}

__global__ void reorder_k(const void* __restrict__ edges_raw, long long E,
                          const int* __restrict__ eflag, int Nn,
                          int* __restrict__ cur, int* __restrict__ csr_src) {
    long long e = (long long)blockIdx.x * blockDim.x + threadIdx.x;
    if (e >= E) return;
    long long s, d;
    load_edge(edges_raw, E, *eflag, e, s, d);
    if (s < 0 || s >= Nn || d < 0 || d >= Nn) return;
    int pos = atomicAdd(&cur[(int)d], 1);
    csr_src[pos] = (int)s;
}

// ------------------------------ gather-sum ----------------------------------
// warp per dst node; lane owns float4 feature chunk; sequential fp32 sums.
// bias == nullptr -> init 0; else init bias[lane*4..].
__global__ void gather_sum_k(const float* __restrict__ feat,
                             const int* __restrict__ off,
                             const int* __restrict__ csr_src,
                             const float* __restrict__ bias,
                             float* __restrict__ out, int Nn) {
    int gt = blockIdx.x * blockDim.x + threadIdx.x;
    int node = gt >> 5;
    if (node >= Nn) return;
    int lane = gt & 31;
    int base = off[node];
    int end  = off[node + 1];
    float4 acc = make_float4(0.f, 0.f, 0.f, 0.f);
    if (bias) acc = *(const float4*)(bias + lane * 4);
    for (int j = base; j < end; ++j) {
        int s = csr_src[j];
        float4 v = *(const float4*)(feat + (size_t)s * DIM + lane * 4);
        acc.x += v.x; acc.y += v.y; acc.z += v.z; acc.w += v.w;
    }
    *(float4*)(out + (size_t)node * DIM + lane * 4) = acc;
}

// ------------------------------ LSTM cell ----------------------------------
__global__ void lstm_cell_k(const __half* __restrict__ gates,
                            float* __restrict__ c,
                            __half* __restrict__ hh,
                            __half* __restrict__ hlo, int Nn, int write_lo) {
    int idx = blockIdx.x * blockDim.x + threadIdx.x;
    if (idx >= Nn * 32) return;
    int n = idx >> 5;
    int q = (idx & 31) * 4;
    const __half2* gr = (const __half2*)(gates + (size_t)n * NG + q);
    float2 i01 = __half22float2(gr[0]);
    float2 i23 = __half22float2(gr[1]);
    float2 f01 = __half22float2(gr[64]);
    float2 f23 = __half22float2(gr[65]);
    float2 g01 = __half22float2(gr[128]);
    float2 g23 = __half22float2(gr[129]);
    float2 o01 = __half22float2(gr[192]);
    float2 o23 = __half22float2(gr[193]);
    float* cp = c + (size_t)n * DIM + q;
    float4 cv = *(const float4*)cp;
    float4 cn, hn;
    cn.x = sigf(f01.x) * cv.x + sigf(i01.x) * tanh_fast(g01.x);
    cn.y = sigf(f01.y) * cv.y + sigf(i01.y) * tanh_fast(g01.y);
    cn.z = sigf(f23.x) * cv.z + sigf(i23.x) * tanh_fast(g23.x);
    cn.w = sigf(f23.y) * cv.w + sigf(i23.y) * tanh_fast(g23.y);
    hn.x = sigf(o01.x) * tanh_fast(cn.x);
    hn.y = sigf(o01.y) * tanh_fast(cn.y);
    hn.z = sigf(o23.x) * tanh_fast(cn.z);
    hn.w = sigf(o23.y) * tanh_fast(cn.w);
    *(float4*)cp = cn;
    __half2 h01 = __floats2half2_rn(hn.x, hn.y);
    __half2 h23 = __floats2half2_rn(hn.z, hn.w);
    __half2* hhp = (__half2*)(hh + (size_t)n * DIM + q);
    hhp[0] = h01;
    hhp[1] = h23;
    if (write_lo) {
        float2 f0 = __half22float2(h01), f1 = __half22float2(h23);
        __half2* lp = (__half2*)(hlo + (size_t)n * DIM + q);
        lp[0] = __floats2half2_rn(hn.x - f0.x, hn.y - f0.y);
        lp[1] = __floats2half2_rn(hn.z - f1.x, hn.w - f1.y);
    }
}

// ---------------------------------------------------------------------------
// LSTM gate GEMM via mma.sync fp16, SINGLE pass. (R12 mainloop.)
// ---------------------------------------------------------------------------
#define ROWB 80     // bytes per smem row (32 fp16 data + pad)
#define ATILE 10240 // 128 * 80
#define NITER 8

__global__ __launch_bounds__(256, 2) void gemm_lstm_mma(
    const __half* __restrict__ xh, const __half* __restrict__ hh,
    const __half* __restrict__ wc,
    const float* __restrict__ bias,
    __half* __restrict__ C, int M) {
    __shared__ __align__(128) char sm[4 * ATILE];

    int tid  = threadIdx.x;
    int wid  = tid >> 5;
    int lane = tid & 31;
    int m0 = blockIdx.x * 128;
    int n0 = blockIdx.y * 128;

    uint32_t sbase = smem_u32(sm);
    int wm = (wid >> 2) * 64;
    int wn = (wid & 3) * 32;

    int a_row  = (lane & 7) + ((lane >> 3) & 1) * 8;
    int a_kch  = lane >> 4;
    int b_row  = (lane & 7) + (lane >> 4) * 8;
    int b_kch  = (lane >> 3) & 1;

    int r0c = tid >> 2;
    int ch  = (tid & 3);

    float acc[4][4][4];
#pragma unroll
    for (int i = 0; i < 4; ++i)
#pragma unroll
        for (int j = 0; j < 4; ++j)
#pragma unroll
            for (int q = 0; q < 4; ++q) acc[i][j][q] = 0.0f;

    auto issue = [&](int i, int b) {
        int kc = i & 7;
        const __half* Ap = (kc < 4) ? xh : hh;
        int ka = (kc & 3) * 32;
        int kb = kc * 32;

        uint32_t dA = sbase + b * ATILE;
        uint32_t dB = sbase + 2 * ATILE + b * ATILE;
#pragma unroll
        for (int it = 0; it < 2; ++it) {
            int r = r0c + it * 64;
            int gm = m0 + r;
            const __half* src =
                Ap + (size_t)(gm < M ? gm : 0) * DIM + ka + ch * 8;
            cp_async16(dA + r * ROWB + ch * 16, src);
        }
#pragma unroll
        for (int it = 0; it < 2; ++it) {
            int r = r0c + it * 64;
            const __half* src = wc + (size_t)(n0 + r) * 256 + kb + ch * 8;
            cp_async16(dB + r * ROWB + ch * 16, src);
        }
        cp_commit();
    };

    issue(0, 0);

    for (int i = 0; i < NITER; ++i) {
        if (i + 1 < NITER) issue(i + 1, (i + 1) & 1);
        if (i + 1 < NITER) cp_wait1(); else cp_wait0();
        __syncthreads();

        int b = i & 1;
        uint32_t sA = sbase + b * ATILE;
        uint32_t sB = sbase + 2 * ATILE + b * ATILE;

#pragma unroll
        for (int k16 = 0; k16 < 2; ++k16) {
            uint32_t afr[4][4];
            uint32_t bfr[2][4];
#pragma unroll
            for (int fm = 0; fm < 4; ++fm) {
                uint32_t addr = sA + (wm + fm * 16 + a_row) * ROWB
                              + (k16 * 2 + a_kch) * 16;
                ldsm4(afr[fm], addr);
            }
#pragma unroll
            for (int fn2 = 0; fn2 < 2; ++fn2) {
                uint32_t addr = sB + (wn + fn2 * 16 + b_row) * ROWB
                              + (k16 * 2 + b_kch) * 16;
                ldsm4(bfr[fn2], addr);
            }
#pragma unroll
            for (int fm = 0; fm < 4; ++fm) {
#pragma unroll
                for (int fn = 0; fn < 4; ++fn)
                    mma_f16(acc[fm][fn], afr[fm], &bfr[fn >> 1][(fn & 1) * 2]);
            }
        }
        __syncthreads();
    }

    int gid = lane >> 2;
    int tig = lane & 3;
    float2 bfr2[4];
#pragma unroll
    for (int fn = 0; fn < 4; ++fn) {
        int n = n0 + wn + fn * 8 + tig * 2;
        bfr2[fn] = *(const float2*)(bias + n);
    }
#pragma unroll
    for (int fm = 0; fm < 4; ++fm) {
        int mlo = m0 + wm + fm * 16 + gid;
        int mhi = mlo + 8;
#pragma unroll
        for (int fn = 0; fn < 4; ++fn) {
            int n = n0 + wn + fn * 8 + tig * 2;
            if (mlo < M) {
                __half2 o = __floats2half2_rn(acc[fm][fn][0] + bfr2[fn].x,
                                              acc[fm][fn][1] + bfr2[fn].y);
                *(__half2*)(C + (size_t)mlo * NG + n) = o;
            }
            if (mhi < M) {
                __half2 o = __floats2half2_rn(acc[fm][fn][2] + bfr2[fn].x,
                                              acc[fm][fn][3] + bfr2[fn].y);
                *(__half2*)(C + (size_t)mhi * NG + n) = o;
            }
        }
    }
}

// ---------------------------------------------------------------------------
// GCN GEMM: 3-pass split-fp16 (hi*whi + hi*wlo + lo*whi, fp32 acc). (R14.)
// ---------------------------------------------------------------------------
#define GNITER 12

__global__ __launch_bounds__(256, 2) void gemm_gcn_split(
    const __half* __restrict__ ahi, const __half* __restrict__ alo,
    const __half* __restrict__ whi, const __half* __restrict__ wlo,
    float* __restrict__ C, int M) {
    __shared__ __align__(128) char sm[4 * ATILE];

    int tid  = threadIdx.x;
    int wid  = tid >> 5;
    int lane = tid & 31;
    int m0 = blockIdx.x * 128;

    uint32_t sbase = smem_u32(sm);
    int wm = (wid >> 2) * 64;
    int wn = (wid & 3) * 32;

    int a_row  = (lane & 7) + ((lane >> 3) & 1) * 8;
    int a_kch  = lane >> 4;
    int b_row  = (lane & 7) + (lane >> 4) * 8;
    int b_kch  = (lane >> 3) & 1;

    int r0c = tid >> 2;
    int ch  = (tid & 3);

    float acc[4][4][4];
#pragma unroll
    for (int i = 0; i < 4; ++i)
#pragma unroll
        for (int j = 0; j < 4; ++j)
#pragma unroll
            for (int q = 0; q < 4; ++q) acc[i][j][q] = 0.0f;

    auto issue = [&](int i, int b) {
        int pass = i >> 2;
        int kc   = i & 3;
        const __half* Ap = (pass == 2) ? alo : ahi;
        const __half* Wp = (pass == 1) ? wlo : whi;
        int k0 = kc * 32;

        uint32_t dA = sbase + b * ATILE;
        uint32_t dB = sbase + 2 * ATILE + b * ATILE;
#pragma unroll
        for (int it = 0; it < 2; ++it) {
            int r = r0c + it * 64;
            int gm = m0 + r;
            const __half* src =
                Ap + (size_t)(gm < M ? gm : 0) * DIM + k0 + ch * 8;
            cp_async16(dA + r * ROWB + ch * 16, src);
        }
#pragma unroll
        for (int it = 0; it < 2; ++it) {
            int r = r0c + it * 64;
            const __half* src = Wp + (size_t)r * DIM + k0 + ch * 8;
            cp_async16(dB + r * ROWB + ch * 16, src);
        }
        cp_commit();
    };

    issue(0, 0);

    for (int i = 0; i < GNITER; ++i) {
        if (i + 1 < GNITER) issue(i + 1, (i + 1) & 1);
        if (i + 1 < GNITER) cp_wait1(); else cp_wait0();
        __syncthreads();

        int b = i & 1;
        uint32_t sA = sbase + b * ATILE;
        uint32_t sB = sbase + 2 * ATILE + b * ATILE;

#pragma unroll
        for (int k16 = 0; k16 < 2; ++k16) {
            uint32_t afr[4][4];
            uint32_t bfr[2][4];
#pragma unroll
            for (int fm = 0; fm < 4; ++fm) {
                uint32_t addr = sA + (wm + fm * 16 + a_row) * ROWB
                              + (k16 * 2 + a_kch) * 16;
                ldsm4(afr[fm], addr);
            }
#pragma unroll
            for (int fn2 = 0; fn2 < 2; ++fn2) {
                uint32_t addr = sB + (wn + fn2 * 16 + b_row) * ROWB
                              + (k16 * 2 + b_kch) * 16;
                ldsm4(bfr[fn2], addr);
            }
#pragma unroll
            for (int fm = 0; fm < 4; ++fm) {
#pragma unroll
                for (int fn = 0; fn < 4; ++fn)
                    mma_f16(acc[fm][fn], afr[fm], &bfr[fn >> 1][(fn & 1) * 2]);
            }
        }
        __syncthreads();
    }

    int gid = lane >> 2;
    int tig = lane & 3;
#pragma unroll
    for (int fm = 0; fm < 4; ++fm) {
        int mlo = m0 + wm + fm * 16 + gid;
        int mhi = mlo + 8;
#pragma unroll
        for (int fn = 0; fn < 4; ++fn) {
            int n = wn + fn * 8 + tig * 2;
            if (mlo < M)
                *(float2*)(C + (size_t)mlo * DIM + n) =
                    make_float2(acc[fm][fn][0], acc[fm][fn][1]);
            if (mhi < M)
                *(float2*)(C + (size_t)mhi * DIM + n) =
                    make_float2(acc[fm][fn][2], acc[fm][fn][3]);
        }
    }
}

// ------------------------------ host launcher ------------------------------
extern "C" void kernel_launch(void* const* d_in, const int* in_sizes, int n_in,
                              void* d_out, int out_size) {
    const float* input_aux = (const float*)d_in[0];
    const void*  edges     = d_in[1];
    const float* W_ih      = (const float*)d_in[2];
    const float* W_hh      = (const float*)d_in[3];
    const float* b_ih      = (const float*)d_in[4];
    const float* b_hh      = (const float*)d_in[5];
    const float* W1        = (const float*)d_in[6];
    const float* b1        = (const float*)d_in[7];
    const float* W2        = (const float*)d_in[8];
    const float* b2        = (const float*)d_in[9];
    float* out = (float*)d_out;

    int Nn  = out_size / DIM;
    int seq = in_sizes[0] / (Nn * DIM);
    long long E = (long long)in_sizes[1] / 2;

    float *c, *t1, *t2, *bsum;
    __half *gates, *xh, *hh, *hlo, *wc;
    __half *w1thi, *w1tlo, *w2thi, *w2tlo;
    int *eflag, *deg, *off, *cur, *csr_src;
    cudaGetSymbolAddress((void**)&c,       g_c);
    cudaGetSymbolAddress((void**)&gates,   g_gates);
    cudaGetSymbolAddress((void**)&t1,      g_t1);
    cudaGetSymbolAddress((void**)&t2,      g_t2);
    cudaGetSymbolAddress((void**)&bsum,    g_bsum);
    cudaGetSymbolAddress((void**)&eflag,   g_eflag);
    cudaGetSymbolAddress((void**)&deg,     g_deg);
    cudaGetSymbolAddress((void**)&off,     g_off);
    cudaGetSymbolAddress((void**)&cur,     g_cur);
    cudaGetSymbolAddress((void**)&csr_src, g_csr_src);
    cudaGetSymbolAddress((void**)&xh,      g_xh);
    cudaGetSymbolAddress((void**)&hh,      g_hh);
    cudaGetSymbolAddress((void**)&hlo,     g_hlo);
    cudaGetSymbolAddress((void**)&wc,      g_wc);
    cudaGetSymbolAddress((void**)&w1thi,   g_w1thi);
    cudaGetSymbolAddress((void**)&w1tlo,   g_w1tlo);
    cudaGetSymbolAddress((void**)&w2thi,   g_w2thi);
    cudaGetSymbolAddress((void**)&w2tlo,   g_w2tlo);

    int nd = Nn * DIM;
    int eb = 256;
    unsigned eblocks = (unsigned)((E + eb - 1) / eb);

    detect_edge_dtype_k<<<1, 256>>>((const int*)edges, 2 * E, eflag);
    bias_sum_k<<<1, NG>>>(b_ih, b_hh, bsum);
    fill_zero_k<<<(nd + eb - 1) / eb, eb>>>(c, nd);
    fill_zero_k<<<(nd / 2 + eb - 1) / eb, eb>>>((float*)hh, nd / 2);

    // CSR build over dst (shared by both GCN layers)
    fill_zero_int_k<<<(Nn + eb - 1) / eb, eb>>>(deg, Nn);
    hist_k<<<eblocks, eb>>>(edges, E, eflag, Nn, deg);
    scan_k<<<1, 1024>>>(deg, off, Nn);
    copy_int_k<<<(Nn + eb - 1) / eb, eb>>>(off, cur, Nn);
    reorder_k<<<eblocks, eb>>>(edges, E, eflag, Nn, cur, csr_src);

    int xn4 = (seq * nd) / 4;
    cvt_half_k<<<(xn4 + eb - 1) / eb, eb>>>(input_aux, xh, xn4);
    build_wcat_k<<<(NG * 256 + eb - 1) / eb, eb>>>(W_ih, W_hh, wc);
    build_wt_k<<<(DIM * DIM + eb - 1) / eb, eb>>>(W1, w1thi, w1tlo);
    build_wt_k<<<(DIM * DIM + eb - 1) / eb, eb>>>(W2, w2thi, w2tlo);

    dim3 ggate((Nn + 127) / 128, 4);
    int cell_threads = Nn * 32;
    for (int t = 0; t < seq; ++t) {
        const __half* xt = xh + (size_t)t * nd;
        gemm_lstm_mma<<<ggate, 256>>>(xt, hh, wc, bsum, gates, Nn);
        lstm_cell_k<<<(cell_threads + eb - 1) / eb, eb>>>(
            gates, c, hh, hlo, Nn, (t == seq - 1) ? 1 : 0);
    }

    dim3 ggcn((Nn + 127) / 128, 1);
    unsigned gblocks = (unsigned)(((long long)Nn * 32 + eb - 1) / eb);

    // GCN layer 1: t1 = h @ W1 (split fp16); t2 = gather-sum(t1);
    // relu+bias -> hh/hlo (reused as layer-2 input).
    gemm_gcn_split<<<ggcn, 256>>>(hh, hlo, w1thi, w1tlo, t1, Nn);
    gather_sum_k<<<gblocks, eb>>>(t1, off, csr_src, (const float*)nullptr, t2, Nn);
    relu_bias_split_k<<<(nd / 4 + eb - 1) / eb, eb>>>(t2, b1, hh, hlo, nd / 4);

    // GCN layer 2: t2 = relu_out @ W2 (split fp16); out = gather-sum(t2) + b2
    gemm_gcn_split<<<ggcn, 256>>>(hh, hlo, w2thi, w2tlo, t2, Nn);
    gather_sum_k<<<gblocks, eb>>>(t2, off, csr_src, b2, out, Nn);
}

// round 16
// speedup vs baseline: 1.2061x; 1.0217x over previous
#include <cuda_runtime.h>
#include <cuda_bf16.h>
#include <cuda_fp16.h>
#include <math.h>
#include <stdint.h>

// ---------------------------------------------------------------------------
// lstm_gcn round 16: R15 base + fp16 GCN feature pipeline:
//   gemm_gcn_split writes fp16; CSR gathers read fp16 (halves L2 traffic),
//   accumulate fp32; relu+bias+split fused into layer-1 gather, +bias into
//   layer-2 gather. t1/t2 fp32 buffers eliminated.
// ---------------------------------------------------------------------------

#define MAXN   50000
#define MAXE   1600000
#define MAXSEQ 16
#define DIM    128
#define NG     512

__device__ float  g_c[MAXN * DIM];
__device__ __half g_gates[MAXN * NG];   // also reused: t1h / t2h fp16 buffers
__device__ float  g_bsum[NG];
__device__ int    g_eflag;

__device__ int    g_deg[MAXN];
__device__ int    g_off[MAXN + 1];
__device__ int    g_cur[MAXN];
__device__ int    g_csr_src[MAXE];

__device__ __half g_xh[MAXSEQ * MAXN * DIM];   // x in fp16
__device__ __half g_hh[MAXN * DIM];            // h fp16 (hi)
__device__ __half g_hlo[MAXN * DIM];           // h fp16 residual (last step)
__device__ __half g_wc[NG * 256];              // [512][256] = [W_ih | W_hh] fp16
__device__ __half g_w1thi[DIM * DIM];          // W1^T hi  [n][k]
__device__ __half g_w1tlo[DIM * DIM];          // W1^T lo
__device__ __half g_w2thi[DIM * DIM];          // W2^T hi
__device__ __half g_w2tlo[DIM * DIM];          // W2^T lo
__device__ __half g_t2h[MAXN * DIM];           // layer-2 gemm out fp16

// ------------------------------ helpers ------------------------------------
__device__ __forceinline__ uint32_t smem_u32(const void* p) {
    uint32_t a;
    asm("{ .reg .u64 t; cvta.to.shared.u64 t, %1; cvt.u32.u64 %0, t; }"
        : "=r"(a) : "l"(p));
    return a;
}

__device__ __forceinline__ void ldsm4(uint32_t* r, uint32_t addr) {
    asm volatile("ldmatrix.sync.aligned.m8n8.x4.shared.b16 {%0,%1,%2,%3}, [%4];"
                 : "=r"(r[0]), "=r"(r[1]), "=r"(r[2]), "=r"(r[3]) : "r"(addr));
}

__device__ __forceinline__ void mma_f16(float* d, const uint32_t* a,
                                        const uint32_t* b) {
    asm volatile(
        "mma.sync.aligned.m16n8k16.row.col.f32.f16.f16.f32 "
        "{%0,%1,%2,%3}, {%4,%5,%6,%7}, {%8,%9}, {%0,%1,%2,%3};"
        : "+f"(d[0]), "+f"(d[1]), "+f"(d[2]), "+f"(d[3])
        : "r"(a[0]), "r"(a[1]), "r"(a[2]), "r"(a[3]), "r"(b[0]), "r"(b[1]));
}

__device__ __forceinline__ void cp_async16(uint32_t dst, const void* src) {
    asm volatile("cp.async.cg.shared.global [%0], [%1], 16;"
                 :: "r"(dst), "l"(src));
}
__device__ __forceinline__ void cp_commit() {
    asm volatile("cp.async.commit_group;");
}
__device__ __forceinline__ void cp_wait1() {
    asm volatile("cp.async.wait_group 1;");
}
__device__ __forceinline__ void cp_wait0() {
    asm volatile("cp.async.wait_group 0;");
}

// HW tanh (MUFU.TANH), rel err ~2^-11
__device__ __forceinline__ float tanh_fast(float x) {
    float y;
    asm("tanh.approx.f32 %0, %1;" : "=f"(y) : "f"(x));
    return y;
}
__device__ __forceinline__ float sigf(float x) {
    return fmaf(tanh_fast(0.5f * x), 0.5f, 0.5f);
}

// read edge endpoint pair, dtype-flag dispatched
__device__ __forceinline__ void load_edge(const void* edges_raw, long long E,
                                          int eflag, long long e,
                                          long long& s, long long& d) {
    if (eflag) {
        const long long* ed = (const long long*)edges_raw;
        s = ed[e];
        d = ed[E + e];
    } else {
        const int* ed = (const int*)edges_raw;
        s = ed[e];
        d = ed[E + e];
    }
}

// ------------------------------ edge dtype detect --------------------------
__global__ void detect_edge_dtype_k(const int* __restrict__ e32, long long n32,
                                    int* __restrict__ flag) {
    __shared__ int nz;
    if (threadIdx.x == 0) nz = 0;
    __syncthreads();
    for (long long i = threadIdx.x; i < 4096; i += blockDim.x) {
        long long idx = 2 * i + 1;
        if (idx < n32 && e32[idx] != 0) atomicOr(&nz, 1);
    }
    __syncthreads();
    if (threadIdx.x == 0) *flag = (nz == 0) ? 1 : 0;
}

// ------------------------------ small kernels ------------------------------
__global__ void fill_zero_k(float* __restrict__ p, int n) {
    int i = blockIdx.x * blockDim.x + threadIdx.x;
    if (i < n) p[i] = 0.0f;
}

__global__ void fill_zero_int_k(int* __restrict__ p, int n) {
    int i = blockIdx.x * blockDim.x + threadIdx.x;
    if (i < n) p[i] = 0;
}

__global__ void copy_int_k(const int* __restrict__ a, int* __restrict__ b, int n) {
    int i = blockIdx.x * blockDim.x + threadIdx.x;
    if (i < n) b[i] = a[i];
}

__global__ void bias_sum_k(const float* __restrict__ a, const float* __restrict__ b,
                           float* __restrict__ o) {
    int i = threadIdx.x;
    o[i] = a[i] + b[i];
}

// fp32 -> fp16 convert (vectorized x4)
__global__ void cvt_half_k(const float* __restrict__ src,
                           __half* __restrict__ dst, int n4) {
    int i = blockIdx.x * blockDim.x + threadIdx.x;
    if (i >= n4) return;
    float4 v = ((const float4*)src)[i];
    __half2* dp = (__half2*)(dst + (size_t)i * 4);
    dp[0] = __floats2half2_rn(v.x, v.y);
    dp[1] = __floats2half2_rn(v.z, v.w);
}

// Wcat[512][256] = [W_ih | W_hh] in fp16
__global__ void build_wcat_k(const float* __restrict__ wih, const float* __restrict__ whh,
                             __half* __restrict__ wc) {
    int idx = blockIdx.x * blockDim.x + threadIdx.x;
    if (idx >= NG * 256) return;
    int n = idx >> 8, k = idx & 255;
    float v = (k < 128) ? wih[n * 128 + k] : whh[n * 128 + (k - 128)];
    wc[idx] = __float2half_rn(v);
}

// W^T hi/lo: wt[n][k] = W[k][n] split into fp16 hi + residual
__global__ void build_wt_k(const float* __restrict__ w,
                           __half* __restrict__ hi, __half* __restrict__ lo) {
    int idx = blockIdx.x * blockDim.x + threadIdx.x;
    if (idx >= DIM * DIM) return;
    int n = idx >> 7, k = idx & 127;
    float v = w[k * DIM + n];
    __half h = __float2half_rn(v);
    hi[idx] = h;
    lo[idx] = __float2half_rn(v - __half2float(h));
}

// ------------------------------ CSR build ----------------------------------
__global__ void hist_k(const void* __restrict__ edges_raw, long long E,
                       const int* __restrict__ eflag, int Nn,
                       int* __restrict__ deg) {
    long long e = (long long)blockIdx.x * blockDim.x + threadIdx.x;
    if (e >= E) return;
    long long s, d;
    load_edge(edges_raw, E, *eflag, e, s, d);
    if (s < 0 || s >= Nn || d < 0 || d >= Nn) return;
    atomicAdd(&deg[(int)d], 1);
}

// single-block exclusive scan of deg[0..n) -> off[0..n]
__global__ void scan_k(const int* __restrict__ deg, int* __restrict__ off, int n) {
    __shared__ int carry;
    __shared__ int buf[1024];
    if (threadIdx.x == 0) carry = 0;
    __syncthreads();
    for (int base = 0; base < n; base += 1024) {
        int i = base + threadIdx.x;
        int v = (i < n) ? deg[i] : 0;
        buf[threadIdx.x] = v;
        __syncthreads();
#pragma unroll
        for (int s = 1; s < 1024; s <<= 1) {
            int t = (threadIdx.x >= s) ? buf[threadIdx.x - s] : 0;
            __syncthreads();
            buf[threadIdx.x] += t;
            __syncthreads();
        }
        if (i < n) off[i] = carry + buf[threadIdx.x] - v;
        __syncthreads();
        if (threadIdx.x == 1023) carry += buf[1023];
        __syncthreads();
    }
    if (threadIdx.x == 0) off[n] = carry;
}

__global__ void reorder_k(const void* __restrict__ edges_raw, long long E,
                          const int* __restrict__ eflag, int Nn,
                          int* __restrict__ cur, int* __restrict__ csr_src) {
    long long e = (long long)blockIdx.x * blockDim.x + threadIdx.x;
    if (e >= E) return;
    long long s, d;
    load_edge(edges_raw, E, *eflag, e, s, d);
    if (s < 0 || s >= Nn || d < 0 || d >= Nn) return;
    int pos = atomicAdd(&cur[(int)d], 1);
    csr_src[pos] = (int)s;
}

// ------------------------------ gathers (fp16 feat) -------------------------
// warp per dst node; lane owns 4 features (8B fp16). fp32 accumulation.
// layer 1: out = relu(sum + b1) split into fp16 hi/lo
__global__ void gather_relu_split_k(const __half* __restrict__ feat,
                                    const int* __restrict__ off,
                                    const int* __restrict__ csr_src,
                                    const float* __restrict__ bias,
                                    __half* __restrict__ hi,
                                    __half* __restrict__ lo, int Nn) {
    int gt = blockIdx.x * blockDim.x + threadIdx.x;
    int node = gt >> 5;
    if (node >= Nn) return;
    int lane = gt & 31;
    float4 acc = *(const float4*)(bias + lane * 4);
    int base = off[node];
    int end  = off[node + 1];
    for (int j = base; j < end; ++j) {
        int s = csr_src[j];
        const __half2* fp = (const __half2*)(feat + (size_t)s * DIM + lane * 4);
        float2 a = __half22float2(fp[0]);
        float2 b = __half22float2(fp[1]);
        acc.x += a.x; acc.y += a.y; acc.z += b.x; acc.w += b.y;
    }
    acc.x = fmaxf(acc.x, 0.0f);
    acc.y = fmaxf(acc.y, 0.0f);
    acc.z = fmaxf(acc.z, 0.0f);
    acc.w = fmaxf(acc.w, 0.0f);
    __half2 h0 = __floats2half2_rn(acc.x, acc.y);
    __half2 h1 = __floats2half2_rn(acc.z, acc.w);
    float2 f0 = __half22float2(h0), f1 = __half22float2(h1);
    __half2* hp = (__half2*)(hi + (size_t)node * DIM + lane * 4);
    __half2* lp = (__half2*)(lo + (size_t)node * DIM + lane * 4);
    hp[0] = h0; hp[1] = h1;
    lp[0] = __floats2half2_rn(acc.x - f0.x, acc.y - f0.y);
    lp[1] = __floats2half2_rn(acc.z - f1.x, acc.w - f1.y);
}

// layer 2: out = sum + b2 (fp32 final output)
__global__ void gather_bias_k(const __half* __restrict__ feat,
                              const int* __restrict__ off,
                              const int* __restrict__ csr_src,
                              const float* __restrict__ bias,
                              float* __restrict__ out, int Nn) {
    int gt = blockIdx.x * blockDim.x + threadIdx.x;
    int node = gt >> 5;
    if (node >= Nn) return;
    int lane = gt & 31;
    float4 acc = *(const float4*)(bias + lane * 4);
    int base = off[node];
    int end  = off[node + 1];
    for (int j = base; j < end; ++j) {
        int s = csr_src[j];
        const __half2* fp = (const __half2*)(feat + (size_t)s * DIM + lane * 4);
        float2 a = __half22float2(fp[0]);
        float2 b = __half22float2(fp[1]);
        acc.x += a.x; acc.y += a.y; acc.z += b.x; acc.w += b.y;
    }
    *(float4*)(out + (size_t)node * DIM + lane * 4) = acc;
}

// ------------------------------ LSTM cell ----------------------------------
__global__ void lstm_cell_k(const __half* __restrict__ gates,
                            float* __restrict__ c,
                            __half* __restrict__ hh,
                            __half* __restrict__ hlo, int Nn, int write_lo) {
    int idx = blockIdx.x * blockDim.x + threadIdx.x;
    if (idx >= Nn * 32) return;
    int n = idx >> 5;
    int q = (idx & 31) * 4;
    const __half2* gr = (const __half2*)(gates + (size_t)n * NG + q);
    float2 i01 = __half22float2(gr[0]);
    float2 i23 = __half22float2(gr[1]);
    float2 f01 = __half22float2(gr[64]);
    float2 f23 = __half22float2(gr[65]);
    float2 g01 = __half22float2(gr[128]);
    float2 g23 = __half22float2(gr[129]);
    float2 o01 = __half22float2(gr[192]);
    float2 o23 = __half22float2(gr[193]);
    float* cp = c + (size_t)n * DIM + q;
    float4 cv = *(const float4*)cp;
    float4 cn, hn;
    cn.x = sigf(f01.x) * cv.x + sigf(i01.x) * tanh_fast(g01.x);
    cn.y = sigf(f01.y) * cv.y + sigf(i01.y) * tanh_fast(g01.y);
    cn.z = sigf(f23.x) * cv.z + sigf(i23.x) * tanh_fast(g23.x);
    cn.w = sigf(f23.y) * cv.w + sigf(i23.y) * tanh_fast(g23.y);
    hn.x = sigf(o01.x) * tanh_fast(cn.x);
    hn.y = sigf(o01.y) * tanh_fast(cn.y);
    hn.z = sigf(o23.x) * tanh_fast(cn.z);
    hn.w = sigf(o23.y) * tanh_fast(cn.w);
    *(float4*)cp = cn;
    __half2 h01 = __floats2half2_rn(hn.x, hn.y);
    __half2 h23 = __floats2half2_rn(hn.z, hn.w);
    __half2* hhp = (__half2*)(hh + (size_t)n * DIM + q);
    hhp[0] = h01;
    hhp[1] = h23;
    if (write_lo) {
        float2 f0 = __half22float2(h01), f1 = __half22float2(h23);
        __half2* lp = (__half2*)(hlo + (size_t)n * DIM + q);
        lp[0] = __floats2half2_rn(hn.x - f0.x, hn.y - f0.y);
        lp[1] = __floats2half2_rn(hn.z - f1.x, hn.w - f1.y);
    }
}

// ---------------------------------------------------------------------------
// LSTM gate GEMM via mma.sync fp16, SINGLE pass. (R12 mainloop.)
// ---------------------------------------------------------------------------
#define ROWB 80     // bytes per smem row (32 fp16 data + pad)
#define ATILE 10240 // 128 * 80
#define NITER 8

__global__ __launch_bounds__(256, 2) void gemm_lstm_mma(
    const __half* __restrict__ xh, const __half* __restrict__ hh,
    const __half* __restrict__ wc,
    const float* __restrict__ bias,
    __half* __restrict__ C, int M) {
    __shared__ __align__(128) char sm[4 * ATILE];

    int tid  = threadIdx.x;
    int wid  = tid >> 5;
    int lane = tid & 31;
    int m0 = blockIdx.x * 128;
    int n0 = blockIdx.y * 128;

    uint32_t sbase = smem_u32(sm);
    int wm = (wid >> 2) * 64;
    int wn = (wid & 3) * 32;

    int a_row  = (lane & 7) + ((lane >> 3) & 1) * 8;
    int a_kch  = lane >> 4;
    int b_row  = (lane & 7) + (lane >> 4) * 8;
    int b_kch  = (lane >> 3) & 1;

    int r0c = tid >> 2;
    int ch  = (tid & 3);

    float acc[4][4][4];
#pragma unroll
    for (int i = 0; i < 4; ++i)
#pragma unroll
        for (int j = 0; j < 4; ++j)
#pragma unroll
            for (int q = 0; q < 4; ++q) acc[i][j][q] = 0.0f;

    auto issue = [&](int i, int b) {
        int kc = i & 7;
        const __half* Ap = (kc < 4) ? xh : hh;
        int ka = (kc & 3) * 32;
        int kb = kc * 32;

        uint32_t dA = sbase + b * ATILE;
        uint32_t dB = sbase + 2 * ATILE + b * ATILE;
#pragma unroll
        for (int it = 0; it < 2; ++it) {
            int r = r0c + it * 64;
            int gm = m0 + r;
            const __half* src =
                Ap + (size_t)(gm < M ? gm : 0) * DIM + ka + ch * 8;
            cp_async16(dA + r * ROWB + ch * 16, src);
        }
#pragma unroll
        for (int it = 0; it < 2; ++it) {
            int r = r0c + it * 64;
            const __half* src = wc + (size_t)(n0 + r) * 256 + kb + ch * 8;
            cp_async16(dB + r * ROWB + ch * 16, src);
        }
        cp_commit();
    };

    issue(0, 0);

    for (int i = 0; i < NITER; ++i) {
        if (i + 1 < NITER) issue(i + 1, (i + 1) & 1);
        if (i + 1 < NITER) cp_wait1(); else cp_wait0();
        __syncthreads();

        int b = i & 1;
        uint32_t sA = sbase + b * ATILE;
        uint32_t sB = sbase + 2 * ATILE + b * ATILE;

#pragma unroll
        for (int k16 = 0; k16 < 2; ++k16) {
            uint32_t afr[4][4];
            uint32_t bfr[2][4];
#pragma unroll
            for (int fm = 0; fm < 4; ++fm) {
                uint32_t addr = sA + (wm + fm * 16 + a_row) * ROWB
                              + (k16 * 2 + a_kch) * 16;
                ldsm4(afr[fm], addr);
            }
#pragma unroll
            for (int fn2 = 0; fn2 < 2; ++fn2) {
                uint32_t addr = sB + (wn + fn2 * 16 + b_row) * ROWB
                              + (k16 * 2 + b_kch) * 16;
                ldsm4(bfr[fn2], addr);
            }
#pragma unroll
            for (int fm = 0; fm < 4; ++fm) {
#pragma unroll
                for (int fn = 0; fn < 4; ++fn)
                    mma_f16(acc[fm][fn], afr[fm], &bfr[fn >> 1][(fn & 1) * 2]);
            }
        }
        __syncthreads();
    }

    int gid = lane >> 2;
    int tig = lane & 3;
    float2 bfr2[4];
#pragma unroll
    for (int fn = 0; fn < 4; ++fn) {
        int n = n0 + wn + fn * 8 + tig * 2;
        bfr2[fn] = *(const float2*)(bias + n);
    }
#pragma unroll
    for (int fm = 0; fm < 4; ++fm) {
        int mlo = m0 + wm + fm * 16 + gid;
        int mhi = mlo + 8;
#pragma unroll
        for (int fn = 0; fn < 4; ++fn) {
            int n = n0 + wn + fn * 8 + tig * 2;
            if (mlo < M) {
                __half2 o = __floats2half2_rn(acc[fm][fn][0] + bfr2[fn].x,
                                              acc[fm][fn][1] + bfr2[fn].y);
                *(__half2*)(C + (size_t)mlo * NG + n) = o;
            }
            if (mhi < M) {
                __half2 o = __floats2half2_rn(acc[fm][fn][2] + bfr2[fn].x,
                                              acc[fm][fn][3] + bfr2[fn].y);
                *(__half2*)(C + (size_t)mhi * NG + n) = o;
            }
        }
    }
}

// ---------------------------------------------------------------------------
// GCN GEMM: 3-pass split-fp16, fp32 acc, fp16 output.
// ---------------------------------------------------------------------------
#define GNITER 12

__global__ __launch_bounds__(256, 2) void gemm_gcn_split(
    const __half* __restrict__ ahi, const __half* __restrict__ alo,
    const __half* __restrict__ whi, const __half* __restrict__ wlo,
    __half* __restrict__ C, int M) {
    __shared__ __align__(128) char sm[4 * ATILE];

    int tid  = threadIdx.x;
    int wid  = tid >> 5;
    int lane = tid & 31;
    int m0 = blockIdx.x * 128;

    uint32_t sbase = smem_u32(sm);
    int wm = (wid >> 2) * 64;
    int wn = (wid & 3) * 32;

    int a_row  = (lane & 7) + ((lane >> 3) & 1) * 8;
    int a_kch  = lane >> 4;
    int b_row  = (lane & 7) + (lane >> 4) * 8;
    int b_kch  = (lane >> 3) & 1;

    int r0c = tid >> 2;
    int ch  = (tid & 3);

    float acc[4][4][4];
#pragma unroll
    for (int i = 0; i < 4; ++i)
#pragma unroll
        for (int j = 0; j < 4; ++j)
#pragma unroll
            for (int q = 0; q < 4; ++q) acc[i][j][q] = 0.0f;

    auto issue = [&](int i, int b) {
        int pass = i >> 2;
        int kc   = i & 3;
        const __half* Ap = (pass == 2) ? alo : ahi;
        const __half* Wp = (pass == 1) ? wlo : whi;
        int k0 = kc * 32;

        uint32_t dA = sbase + b * ATILE;
        uint32_t dB = sbase + 2 * ATILE + b * ATILE;
#pragma unroll
        for (int it = 0; it < 2; ++it) {
            int r = r0c + it * 64;
            int gm = m0 + r;
            const __half* src =
                Ap + (size_t)(gm < M ? gm : 0) * DIM + k0 + ch * 8;
            cp_async16(dA + r * ROWB + ch * 16, src);
        }
#pragma unroll
        for (int it = 0; it < 2; ++it) {
            int r = r0c + it * 64;
            const __half* src = Wp + (size_t)r * DIM + k0 + ch * 8;
            cp_async16(dB + r * ROWB + ch * 16, src);
        }
        cp_commit();
    };

    issue(0, 0);

    for (int i = 0; i < GNITER; ++i) {
        if (i + 1 < GNITER) issue(i + 1, (i + 1) & 1);
        if (i + 1 < GNITER) cp_wait1(); else cp_wait0();
        __syncthreads();

        int b = i & 1;
        uint32_t sA = sbase + b * ATILE;
        uint32_t sB = sbase + 2 * ATILE + b * ATILE;

#pragma unroll
        for (int k16 = 0; k16 < 2; ++k16) {
            uint32_t afr[4][4];
            uint32_t bfr[2][4];
#pragma unroll
            for (int fm = 0; fm < 4; ++fm) {
                uint32_t addr = sA + (wm + fm * 16 + a_row) * ROWB
                              + (k16 * 2 + a_kch) * 16;
                ldsm4(afr[fm], addr);
            }
#pragma unroll
            for (int fn2 = 0; fn2 < 2; ++fn2) {
                uint32_t addr = sB + (wn + fn2 * 16 + b_row) * ROWB
                              + (k16 * 2 + b_kch) * 16;
                ldsm4(bfr[fn2], addr);
            }
#pragma unroll
            for (int fm = 0; fm < 4; ++fm) {
#pragma unroll
                for (int fn = 0; fn < 4; ++fn)
                    mma_f16(acc[fm][fn], afr[fm], &bfr[fn >> 1][(fn & 1) * 2]);
            }
        }
        __syncthreads();
    }

    int gid = lane >> 2;
    int tig = lane & 3;
#pragma unroll
    for (int fm = 0; fm < 4; ++fm) {
        int mlo = m0 + wm + fm * 16 + gid;
        int mhi = mlo + 8;
#pragma unroll
        for (int fn = 0; fn < 4; ++fn) {
            int n = wn + fn * 8 + tig * 2;
            if (mlo < M)
                *(__half2*)(C + (size_t)mlo * DIM + n) =
                    __floats2half2_rn(acc[fm][fn][0], acc[fm][fn][1]);
            if (mhi < M)
                *(__half2*)(C + (size_t)mhi * DIM + n) =
                    __floats2half2_rn(acc[fm][fn][2], acc[fm][fn][3]);
        }
    }
}

// ------------------------------ host launcher ------------------------------
extern "C" void kernel_launch(void* const* d_in, const int* in_sizes, int n_in,
                              void* d_out, int out_size) {
    const float* input_aux = (const float*)d_in[0];
    const void*  edges     = d_in[1];
    const float* W_ih      = (const float*)d_in[2];
    const float* W_hh      = (const float*)d_in[3];
    const float* b_ih      = (const float*)d_in[4];
    const float* b_hh      = (const float*)d_in[5];
    const float* W1        = (const float*)d_in[6];
    const float* b1        = (const float*)d_in[7];
    const float* W2        = (const float*)d_in[8];
    const float* b2        = (const float*)d_in[9];
    float* out = (float*)d_out;

    int Nn  = out_size / DIM;
    int seq = in_sizes[0] / (Nn * DIM);
    long long E = (long long)in_sizes[1] / 2;

    float *c, *bsum;
    __half *gates, *xh, *hh, *hlo, *wc, *t2h;
    __half *w1thi, *w1tlo, *w2thi, *w2tlo;
    int *eflag, *deg, *off, *cur, *csr_src;
    cudaGetSymbolAddress((void**)&c,       g_c);
    cudaGetSymbolAddress((void**)&gates,   g_gates);
    cudaGetSymbolAddress((void**)&bsum,    g_bsum);
    cudaGetSymbolAddress((void**)&eflag,   g_eflag);
    cudaGetSymbolAddress((void**)&deg,     g_deg);
    cudaGetSymbolAddress((void**)&off,     g_off);
    cudaGetSymbolAddress((void**)&cur,     g_cur);
    cudaGetSymbolAddress((void**)&csr_src, g_csr_src);
    cudaGetSymbolAddress((void**)&xh,      g_xh);
    cudaGetSymbolAddress((void**)&hh,      g_hh);
    cudaGetSymbolAddress((void**)&hlo,     g_hlo);
    cudaGetSymbolAddress((void**)&wc,      g_wc);
    cudaGetSymbolAddress((void**)&w1thi,   g_w1thi);
    cudaGetSymbolAddress((void**)&w1tlo,   g_w1tlo);
    cudaGetSymbolAddress((void**)&w2thi,   g_w2thi);
    cudaGetSymbolAddress((void**)&w2tlo,   g_w2tlo);
    cudaGetSymbolAddress((void**)&t2h,     g_t2h);

    __half* t1h = gates;   // reuse gates buffer after LSTM finishes

    int nd = Nn * DIM;
    int eb = 256;
    unsigned eblocks = (unsigned)((E + eb - 1) / eb);

    detect_edge_dtype_k<<<1, 256>>>((const int*)edges, 2 * E, eflag);
    bias_sum_k<<<1, NG>>>(b_ih, b_hh, bsum);
    fill_zero_k<<<(nd + eb - 1) / eb, eb>>>(c, nd);
    fill_zero_k<<<(nd / 2 + eb - 1) / eb, eb>>>((float*)hh, nd / 2);

    // CSR build over dst (shared by both GCN layers)
    fill_zero_int_k<<<(Nn + eb - 1) / eb, eb>>>(deg, Nn);
    hist_k<<<eblocks, eb>>>(edges, E, eflag, Nn, deg);
    scan_k<<<1, 1024>>>(deg, off, Nn);
    copy_int_k<<<(Nn + eb - 1) / eb, eb>>>(off, cur, Nn);
    reorder_k<<<eblocks, eb>>>(edges, E, eflag, Nn, cur, csr_src);

    int xn4 = (seq * nd) / 4;
    cvt_half_k<<<(xn4 + eb - 1) / eb, eb>>>(input_aux, xh, xn4);
    build_wcat_k<<<(NG * 256 + eb - 1) / eb, eb>>>(W_ih, W_hh, wc);
    build_wt_k<<<(DIM * DIM + eb - 1) / eb, eb>>>(W1, w1thi, w1tlo);
    build_wt_k<<<(DIM * DIM + eb - 1) / eb, eb>>>(W2, w2thi, w2tlo);

    dim3 ggate((Nn + 127) / 128, 4);
    int cell_threads = Nn * 32;
    for (int t = 0; t < seq; ++t) {
        const __half* xt = xh + (size_t)t * nd;
        gemm_lstm_mma<<<ggate, 256>>>(xt, hh, wc, bsum, gates, Nn);
        lstm_cell_k<<<(cell_threads + eb - 1) / eb, eb>>>(
            gates, c, hh, hlo, Nn, (t == seq - 1) ? 1 : 0);
    }

    dim3 ggcn((Nn + 127) / 128, 1);
    unsigned gblocks = (unsigned)(((long long)Nn * 32 + eb - 1) / eb);

    // GCN layer 1: t1h = h @ W1 (fp16); gather+relu+bias -> hh/hlo (split)
    gemm_gcn_split<<<ggcn, 256>>>(hh, hlo, w1thi, w1tlo, t1h, Nn);
    gather_relu_split_k<<<gblocks, eb>>>(t1h, off, csr_src, b1, hh, hlo, Nn);

    // GCN layer 2: t2h = relu_out @ W2 (fp16); out = gather(t2h) + b2
    gemm_gcn_split<<<ggcn, 256>>>(hh, hlo, w2thi, w2tlo, t2h, Nn);
    gather_bias_k<<<gblocks, eb>>>(t2h, off, csr_src, b2, out, Nn);
}

// round 17
// speedup vs baseline: 1.2753x; 1.0574x over previous
#include <cuda_runtime.h>
#include <cuda_bf16.h>
#include <cuda_fp16.h>
#include <math.h>
#include <stdint.h>

// ---------------------------------------------------------------------------
// lstm_gcn round 17: R16 base + (1) gate GEMM reads fp32 x directly
// (inline LDG+cvt+STS; kills the 615MB cvt_half_k round-trip) and
// (2) 3-stage cp.async pipeline with ONE barrier per k-iteration.
// ---------------------------------------------------------------------------

#define MAXN   50000
#define MAXE   1600000
#define DIM    128
#define NG     512

__device__ float  g_c[MAXN * DIM];
__device__ __half g_gates[MAXN * NG];   // reused as t1h after LSTM
__device__ float  g_bsum[NG];
__device__ int    g_eflag;

__device__ int    g_deg[MAXN];
__device__ int    g_off[MAXN + 1];
__device__ int    g_cur[MAXN];
__device__ int    g_csr_src[MAXE];

__device__ __half g_hh[MAXN * DIM];            // h fp16 (hi)
__device__ __half g_hlo[MAXN * DIM];           // h fp16 residual (last step)
__device__ __half g_wc[NG * 256];              // [512][256] = [W_ih | W_hh] fp16
__device__ __half g_w1thi[DIM * DIM];          // W1^T hi  [n][k]
__device__ __half g_w1tlo[DIM * DIM];          // W1^T lo
__device__ __half g_w2thi[DIM * DIM];          // W2^T hi
__device__ __half g_w2tlo[DIM * DIM];          // W2^T lo
__device__ __half g_t2h[MAXN * DIM];           // layer-2 gemm out fp16

// ------------------------------ helpers ------------------------------------
__device__ __forceinline__ uint32_t smem_u32(const void* p) {
    uint32_t a;
    asm("{ .reg .u64 t; cvta.to.shared.u64 t, %1; cvt.u32.u64 %0, t; }"
        : "=r"(a) : "l"(p));
    return a;
}

__device__ __forceinline__ void ldsm4(uint32_t* r, uint32_t addr) {
    asm volatile("ldmatrix.sync.aligned.m8n8.x4.shared.b16 {%0,%1,%2,%3}, [%4];"
                 : "=r"(r[0]), "=r"(r[1]), "=r"(r[2]), "=r"(r[3]) : "r"(addr));
}

__device__ __forceinline__ void mma_f16(float* d, const uint32_t* a,
                                        const uint32_t* b) {
    asm volatile(
        "mma.sync.aligned.m16n8k16.row.col.f32.f16.f16.f32 "
        "{%0,%1,%2,%3}, {%4,%5,%6,%7}, {%8,%9}, {%0,%1,%2,%3};"
        : "+f"(d[0]), "+f"(d[1]), "+f"(d[2]), "+f"(d[3])
        : "r"(a[0]), "r"(a[1]), "r"(a[2]), "r"(a[3]), "r"(b[0]), "r"(b[1]));
}

__device__ __forceinline__ void cp_async16(uint32_t dst, const void* src) {
    asm volatile("cp.async.cg.shared.global [%0], [%1], 16;"
                 :: "r"(dst), "l"(src));
}
__device__ __forceinline__ void cp_commit() {
    asm volatile("cp.async.commit_group;");
}
__device__ __forceinline__ void cp_wait1() {
    asm volatile("cp.async.wait_group 1;");
}
__device__ __forceinline__ void cp_wait0() {
    asm volatile("cp.async.wait_group 0;");
}

// HW tanh (MUFU.TANH), rel err ~2^-11
__device__ __forceinline__ float tanh_fast(float x) {
    float y;
    asm("tanh.approx.f32 %0, %1;" : "=f"(y) : "f"(x));
    return y;
}
__device__ __forceinline__ float sigf(float x) {
    return fmaf(tanh_fast(0.5f * x), 0.5f, 0.5f);
}

// read edge endpoint pair, dtype-flag dispatched
__device__ __forceinline__ void load_edge(const void* edges_raw, long long E,
                                          int eflag, long long e,
                                          long long& s, long long& d) {
    if (eflag) {
        const long long* ed = (const long long*)edges_raw;
        s = ed[e];
        d = ed[E + e];
    } else {
        const int* ed = (const int*)edges_raw;
        s = ed[e];
        d = ed[E + e];
    }
}

// ------------------------------ edge dtype detect --------------------------
__global__ void detect_edge_dtype_k(const int* __restrict__ e32, long long n32,
                                    int* __restrict__ flag) {
    __shared__ int nz;
    if (threadIdx.x == 0) nz = 0;
    __syncthreads();
    for (long long i = threadIdx.x; i < 4096; i += blockDim.x) {
        long long idx = 2 * i + 1;
        if (idx < n32 && e32[idx] != 0) atomicOr(&nz, 1);
    }
    __syncthreads();
    if (threadIdx.x == 0) *flag = (nz == 0) ? 1 : 0;
}

// ------------------------------ small kernels ------------------------------
__global__ void fill_zero_k(float* __restrict__ p, int n) {
    int i = blockIdx.x * blockDim.x + threadIdx.x;
    if (i < n) p[i] = 0.0f;
}

__global__ void fill_zero_int_k(int* __restrict__ p, int n) {
    int i = blockIdx.x * blockDim.x + threadIdx.x;
    if (i < n) p[i] = 0;
}

__global__ void copy_int_k(const int* __restrict__ a, int* __restrict__ b, int n) {
    int i = blockIdx.x * blockDim.x + threadIdx.x;
    if (i < n) b[i] = a[i];
}

__global__ void bias_sum_k(const float* __restrict__ a, const float* __restrict__ b,
                           float* __restrict__ o) {
    int i = threadIdx.x;
    o[i] = a[i] + b[i];
}

// Wcat[512][256] = [W_ih | W_hh] in fp16
__global__ void build_wcat_k(const float* __restrict__ wih, const float* __restrict__ whh,
                             __half* __restrict__ wc) {
    int idx = blockIdx.x * blockDim.x + threadIdx.x;
    if (idx >= NG * 256) return;
    int n = idx >> 8, k = idx & 255;
    float v = (k < 128) ? wih[n * 128 + k] : whh[n * 128 + (k - 128)];
    wc[idx] = __float2half_rn(v);
}

// W^T hi/lo: wt[n][k] = W[k][n] split into fp16 hi + residual
__global__ void build_wt_k(const float* __restrict__ w,
                           __half* __restrict__ hi, __half* __restrict__ lo) {
    int idx = blockIdx.x * blockDim.x + threadIdx.x;
    if (idx >= DIM * DIM) return;
    int n = idx >> 7, k = idx & 127;
    float v = w[k * DIM + n];
    __half h = __float2half_rn(v);
    hi[idx] = h;
    lo[idx] = __float2half_rn(v - __half2float(h));
}

// ------------------------------ CSR build ----------------------------------
__global__ void hist_k(const void* __restrict__ edges_raw, long long E,
                       const int* __restrict__ eflag, int Nn,
                       int* __restrict__ deg) {
    long long e = (long long)blockIdx.x * blockDim.x + threadIdx.x;
    if (e >= E) return;
    long long s, d;
    load_edge(edges_raw, E, *eflag, e, s, d);
    if (s < 0 || s >= Nn || d < 0 || d >= Nn) return;
    atomicAdd(&deg[(int)d], 1);
}

// single-block exclusive scan of deg[0..n) -> off[0..n]
__global__ void scan_k(const int* __restrict__ deg, int* __restrict__ off, int n) {
    __shared__ int carry;
    __shared__ int buf[1024];
    if (threadIdx.x == 0) carry = 0;
    __syncthreads();
    for (int base = 0; base < n; base += 1024) {
        int i = base + threadIdx.x;
        int v = (i < n) ? deg[i] : 0;
        buf[threadIdx.x] = v;
        __syncthreads();
#pragma unroll
        for (int s = 1; s < 1024; s <<= 1) {
            int t = (threadIdx.x >= s) ? buf[threadIdx.x - s] : 0;
            __syncthreads();
            buf[threadIdx.x] += t;
            __syncthreads();
        }
        if (i < n) off[i] = carry + buf[threadIdx.x] - v;
        __syncthreads();
        if (threadIdx.x == 1023) carry += buf[1023];
        __syncthreads();
    }
    if (threadIdx.x == 0) off[n] = carry;
}

__global__ void reorder_k(const void* __restrict__ edges_raw, long long E,
                          const int* __restrict__ eflag, int Nn,
                          int* __restrict__ cur, int* __restrict__ csr_src) {
    long long e = (long long)blockIdx.x * blockDim.x + threadIdx.x;
    if (e >= E) return;
    long long s, d;
    load_edge(edges_raw, E, *eflag, e, s, d);
    if (s < 0 || s >= Nn || d < 0 || d >= Nn) return;
    int pos = atomicAdd(&cur[(int)d], 1);
    csr_src[pos] = (int)s;
}

// ------------------------------ gathers (fp16 feat) -------------------------
__global__ void gather_relu_split_k(const __half* __restrict__ feat,
                                    const int* __restrict__ off,
                                    const int* __restrict__ csr_src,
                                    const float* __restrict__ bias,
                                    __half* __restrict__ hi,
                                    __half* __restrict__ lo, int Nn) {
    int gt = blockIdx.x * blockDim.x + threadIdx.x;
    int node = gt >> 5;
    if (node >= Nn) return;
    int lane = gt & 31;
    float4 acc = *(const float4*)(bias + lane * 4);
    int base = off[node];
    int end  = off[node + 1];
    for (int j = base; j < end; ++j) {
        int s = csr_src[j];
        const __half2* fp = (const __half2*)(feat + (size_t)s * DIM + lane * 4);
        float2 a = __half22float2(fp[0]);
        float2 b = __half22float2(fp[1]);
        acc.x += a.x; acc.y += a.y; acc.z += b.x; acc.w += b.y;
    }
    acc.x = fmaxf(acc.x, 0.0f);
    acc.y = fmaxf(acc.y, 0.0f);
    acc.z = fmaxf(acc.z, 0.0f);
    acc.w = fmaxf(acc.w, 0.0f);
    __half2 h0 = __floats2half2_rn(acc.x, acc.y);
    __half2 h1 = __floats2half2_rn(acc.z, acc.w);
    float2 f0 = __half22float2(h0), f1 = __half22float2(h1);
    __half2* hp = (__half2*)(hi + (size_t)node * DIM + lane * 4);
    __half2* lp = (__half2*)(lo + (size_t)node * DIM + lane * 4);
    hp[0] = h0; hp[1] = h1;
    lp[0] = __floats2half2_rn(acc.x - f0.x, acc.y - f0.y);
    lp[1] = __floats2half2_rn(acc.z - f1.x, acc.w - f1.y);
}

__global__ void gather_bias_k(const __half* __restrict__ feat,
                              const int* __restrict__ off,
                              const int* __restrict__ csr_src,
                              const float* __restrict__ bias,
                              float* __restrict__ out, int Nn) {
    int gt = blockIdx.x * blockDim.x + threadIdx.x;
    int node = gt >> 5;
    if (node >= Nn) return;
    int lane = gt & 31;
    float4 acc = *(const float4*)(bias + lane * 4);
    int base = off[node];
    int end  = off[node + 1];
    for (int j = base; j < end; ++j) {
        int s = csr_src[j];
        const __half2* fp = (const __half2*)(feat + (size_t)s * DIM + lane * 4);
        float2 a = __half22float2(fp[0]);
        float2 b = __half22float2(fp[1]);
        acc.x += a.x; acc.y += a.y; acc.z += b.x; acc.w += b.y;
    }
    *(float4*)(out + (size_t)node * DIM + lane * 4) = acc;
}

// ------------------------------ LSTM cell ----------------------------------
__global__ void lstm_cell_k(const __half* __restrict__ gates,
                            float* __restrict__ c,
                            __half* __restrict__ hh,
                            __half* __restrict__ hlo, int Nn, int write_lo) {
    int idx = blockIdx.x * blockDim.x + threadIdx.x;
    if (idx >= Nn * 32) return;
    int n = idx >> 5;
    int q = (idx & 31) * 4;
    const __half2* gr = (const __half2*)(gates + (size_t)n * NG + q);
    float2 i01 = __half22float2(gr[0]);
    float2 i23 = __half22float2(gr[1]);
    float2 f01 = __half22float2(gr[64]);
    float2 f23 = __half22float2(gr[65]);
    float2 g01 = __half22float2(gr[128]);
    float2 g23 = __half22float2(gr[129]);
    float2 o01 = __half22float2(gr[192]);
    float2 o23 = __half22float2(gr[193]);
    float* cp = c + (size_t)n * DIM + q;
    float4 cv = *(const float4*)cp;
    float4 cn, hn;
    cn.x = sigf(f01.x) * cv.x + sigf(i01.x) * tanh_fast(g01.x);
    cn.y = sigf(f01.y) * cv.y + sigf(i01.y) * tanh_fast(g01.y);
    cn.z = sigf(f23.x) * cv.z + sigf(i23.x) * tanh_fast(g23.x);
    cn.w = sigf(f23.y) * cv.w + sigf(i23.y) * tanh_fast(g23.y);
    hn.x = sigf(o01.x) * tanh_fast(cn.x);
    hn.y = sigf(o01.y) * tanh_fast(cn.y);
    hn.z = sigf(o23.x) * tanh_fast(cn.z);
    hn.w = sigf(o23.y) * tanh_fast(cn.w);
    *(float4*)cp = cn;
    __half2 h01 = __floats2half2_rn(hn.x, hn.y);
    __half2 h23 = __floats2half2_rn(hn.z, hn.w);
    __half2* hhp = (__half2*)(hh + (size_t)n * DIM + q);
    hhp[0] = h01;
    hhp[1] = h23;
    if (write_lo) {
        float2 f0 = __half22float2(h01), f1 = __half22float2(h23);
        __half2* lp = (__half2*)(hlo + (size_t)n * DIM + q);
        lp[0] = __floats2half2_rn(hn.x - f0.x, hn.y - f0.y);
        lp[1] = __floats2half2_rn(hn.z - f1.x, hn.w - f1.y);
    }
}

// ---------------------------------------------------------------------------
// LSTM gate GEMM via mma.sync fp16, single pass, THREE-stage pipeline with
// one barrier per iteration. x read as fp32 directly (inline cvt->smem).
// Block tile 128x128, 8 warps (2x4) of 64x32 warp tiles, BK=32, 8 k-iters.
// ---------------------------------------------------------------------------
#define ROWB 80     // bytes per smem row (32 fp16 data + pad)
#define ATILE 10240 // 128 * 80
#define NITER 8
#define STAGES 3

__global__ __launch_bounds__(256, 2) void gemm_lstm_mma(
    const float* __restrict__ xf, const __half* __restrict__ hh,
    const __half* __restrict__ wc,
    const float* __restrict__ bias,
    __half* __restrict__ C, int M) {
    __shared__ __align__(128) char sm[2 * STAGES * ATILE];  // A0-2, B0-2

    int tid  = threadIdx.x;
    int wid  = tid >> 5;
    int lane = tid & 31;
    int m0 = blockIdx.x * 128;
    int n0 = blockIdx.y * 128;

    uint32_t sbase = smem_u32(sm);
    int wm = (wid >> 2) * 64;
    int wn = (wid & 3) * 32;

    int a_row  = (lane & 7) + ((lane >> 3) & 1) * 8;
    int a_kch  = lane >> 4;
    int b_row  = (lane & 7) + (lane >> 4) * 8;
    int b_kch  = (lane >> 3) & 1;

    int r0c = tid >> 2;
    int ch  = (tid & 3);

    float acc[4][4][4];
#pragma unroll
    for (int i = 0; i < 4; ++i)
#pragma unroll
        for (int j = 0; j < 4; ++j)
#pragma unroll
            for (int q = 0; q < 4; ++q) acc[i][j][q] = 0.0f;

    auto issue = [&](int i) {
        int b = i % STAGES;
        int kc = i & 7;             // 0..3: x (fp32 inline cvt), 4..7: h
        int ka = (kc & 3) * 32;
        int kb = kc * 32;

        uint32_t dB = sbase + (STAGES + b) * ATILE;
        if (kc < 4) {
            // fp32 x: LDG + cvt + plain STS (visible after next barrier)
#pragma unroll
            for (int it = 0; it < 2; ++it) {
                int r = r0c + it * 64;
                int gm = m0 + r;
                const float* src =
                    xf + (size_t)(gm < M ? gm : 0) * DIM + ka + ch * 8;
                float4 v0 = *(const float4*)src;
                float4 v1 = *(const float4*)(src + 4);
                __half2 t0 = __floats2half2_rn(v0.x, v0.y);
                __half2 t1 = __floats2half2_rn(v0.z, v0.w);
                __half2 t2 = __floats2half2_rn(v1.x, v1.y);
                __half2 t3 = __floats2half2_rn(v1.z, v1.w);
                uint4 o;
                o.x = *(uint32_t*)&t0; o.y = *(uint32_t*)&t1;
                o.z = *(uint32_t*)&t2; o.w = *(uint32_t*)&t3;
                *(uint4*)(sm + b * ATILE + r * ROWB + ch * 16) = o;
            }
        } else {
            uint32_t dA = sbase + b * ATILE;
#pragma unroll
            for (int it = 0; it < 2; ++it) {
                int r = r0c + it * 64;
                int gm = m0 + r;
                const __half* src =
                    hh + (size_t)(gm < M ? gm : 0) * DIM + ka + ch * 8;
                cp_async16(dA + r * ROWB + ch * 16, src);
            }
        }
#pragma unroll
        for (int it = 0; it < 2; ++it) {
            int r = r0c + it * 64;
            const __half* src = wc + (size_t)(n0 + r) * 256 + kb + ch * 8;
            cp_async16(dB + r * ROWB + ch * 16, src);
        }
        cp_commit();
    };

    issue(0);
    issue(1);

    for (int i = 0; i < NITER; ++i) {
        if (i + 1 < NITER) cp_wait1(); else cp_wait0();
        __syncthreads();

        int b = i % STAGES;
        uint32_t sA = sbase + b * ATILE;
        uint32_t sB = sbase + (STAGES + b) * ATILE;

#pragma unroll
        for (int k16 = 0; k16 < 2; ++k16) {
            uint32_t afr[4][4];
            uint32_t bfr[2][4];
#pragma unroll
            for (int fm = 0; fm < 4; ++fm) {
                uint32_t addr = sA + (wm + fm * 16 + a_row) * ROWB
                              + (k16 * 2 + a_kch) * 16;
                ldsm4(afr[fm], addr);
            }
#pragma unroll
            for (int fn2 = 0; fn2 < 2; ++fn2) {
                uint32_t addr = sB + (wn + fn2 * 16 + b_row) * ROWB
                              + (k16 * 2 + b_kch) * 16;
                ldsm4(bfr[fn2], addr);
            }
#pragma unroll
            for (int fm = 0; fm < 4; ++fm) {
#pragma unroll
                for (int fn = 0; fn < 4; ++fn)
                    mma_f16(acc[fm][fn], afr[fm], &bfr[fn >> 1][(fn & 1) * 2]);
            }
        }

        if (i + 2 < NITER) issue(i + 2);
    }

    // ---- epilogue: add bias, store fp16 gates ----
    int gid = lane >> 2;
    int tig = lane & 3;
    float2 bfr2[4];
#pragma unroll
    for (int fn = 0; fn < 4; ++fn) {
        int n = n0 + wn + fn * 8 + tig * 2;
        bfr2[fn] = *(const float2*)(bias + n);
    }
#pragma unroll
    for (int fm = 0; fm < 4; ++fm) {
        int mlo = m0 + wm + fm * 16 + gid;
        int mhi = mlo + 8;
#pragma unroll
        for (int fn = 0; fn < 4; ++fn) {
            int n = n0 + wn + fn * 8 + tig * 2;
            if (mlo < M) {
                __half2 o = __floats2half2_rn(acc[fm][fn][0] + bfr2[fn].x,
                                              acc[fm][fn][1] + bfr2[fn].y);
                *(__half2*)(C + (size_t)mlo * NG + n) = o;
            }
            if (mhi < M) {
                __half2 o = __floats2half2_rn(acc[fm][fn][2] + bfr2[fn].x,
                                              acc[fm][fn][3] + bfr2[fn].y);
                *(__half2*)(C + (size_t)mhi * NG + n) = o;
            }
        }
    }
}

// ---------------------------------------------------------------------------
// GCN GEMM: 3-pass split-fp16, fp32 acc, fp16 output. (R16, 2-stage.)
// ---------------------------------------------------------------------------
#define GNITER 12

__global__ __launch_bounds__(256, 2) void gemm_gcn_split(
    const __half* __restrict__ ahi, const __half* __restrict__ alo,
    const __half* __restrict__ whi, const __half* __restrict__ wlo,
    __half* __restrict__ C, int M) {
    __shared__ __align__(128) char sm[4 * ATILE];

    int tid  = threadIdx.x;
    int wid  = tid >> 5;
    int lane = tid & 31;
    int m0 = blockIdx.x * 128;

    uint32_t sbase = smem_u32(sm);
    int wm = (wid >> 2) * 64;
    int wn = (wid & 3) * 32;

    int a_row  = (lane & 7) + ((lane >> 3) & 1) * 8;
    int a_kch  = lane >> 4;
    int b_row  = (lane & 7) + (lane >> 4) * 8;
    int b_kch  = (lane >> 3) & 1;

    int r0c = tid >> 2;
    int ch  = (tid & 3);

    float acc[4][4][4];
#pragma unroll
    for (int i = 0; i < 4; ++i)
#pragma unroll
        for (int j = 0; j < 4; ++j)
#pragma unroll
            for (int q = 0; q < 4; ++q) acc[i][j][q] = 0.0f;

    auto issue = [&](int i, int b) {
        int pass = i >> 2;
        int kc   = i & 3;
        const __half* Ap = (pass == 2) ? alo : ahi;
        const __half* Wp = (pass == 1) ? wlo : whi;
        int k0 = kc * 32;

        uint32_t dA = sbase + b * ATILE;
        uint32_t dB = sbase + 2 * ATILE + b * ATILE;
#pragma unroll
        for (int it = 0; it < 2; ++it) {
            int r = r0c + it * 64;
            int gm = m0 + r;
            const __half* src =
                Ap + (size_t)(gm < M ? gm : 0) * DIM + k0 + ch * 8;
            cp_async16(dA + r * ROWB + ch * 16, src);
        }
#pragma unroll
        for (int it = 0; it < 2; ++it) {
            int r = r0c + it * 64;
            const __half* src = Wp + (size_t)r * DIM + k0 + ch * 8;
            cp_async16(dB + r * ROWB + ch * 16, src);
        }
        cp_commit();
    };

    issue(0, 0);

    for (int i = 0; i < GNITER; ++i) {
        if (i + 1 < GNITER) issue(i + 1, (i + 1) & 1);
        if (i + 1 < GNITER) cp_wait1(); else cp_wait0();
        __syncthreads();

        int b = i & 1;
        uint32_t sA = sbase + b * ATILE;
        uint32_t sB = sbase + 2 * ATILE + b * ATILE;

#pragma unroll
        for (int k16 = 0; k16 < 2; ++k16) {
            uint32_t afr[4][4];
            uint32_t bfr[2][4];
#pragma unroll
            for (int fm = 0; fm < 4; ++fm) {
                uint32_t addr = sA + (wm + fm * 16 + a_row) * ROWB
                              + (k16 * 2 + a_kch) * 16;
                ldsm4(afr[fm], addr);
            }
#pragma unroll
            for (int fn2 = 0; fn2 < 2; ++fn2) {
                uint32_t addr = sB + (wn + fn2 * 16 + b_row) * ROWB
                              + (k16 * 2 + b_kch) * 16;
                ldsm4(bfr[fn2], addr);
            }
#pragma unroll
            for (int fm = 0; fm < 4; ++fm) {
#pragma unroll
                for (int fn = 0; fn < 4; ++fn)
                    mma_f16(acc[fm][fn], afr[fm], &bfr[fn >> 1][(fn & 1) * 2]);
            }
        }
        __syncthreads();
    }

    int gid = lane >> 2;
    int tig = lane & 3;
#pragma unroll
    for (int fm = 0; fm < 4; ++fm) {
        int mlo = m0 + wm + fm * 16 + gid;
        int mhi = mlo + 8;
#pragma unroll
        for (int fn = 0; fn < 4; ++fn) {
            int n = wn + fn * 8 + tig * 2;
            if (mlo < M)
                *(__half2*)(C + (size_t)mlo * DIM + n) =
                    __floats2half2_rn(acc[fm][fn][0], acc[fm][fn][1]);
            if (mhi < M)
                *(__half2*)(C + (size_t)mhi * DIM + n) =
                    __floats2half2_rn(acc[fm][fn][2], acc[fm][fn][3]);
        }
    }
}

// ------------------------------ host launcher ------------------------------
extern "C" void kernel_launch(void* const* d_in, const int* in_sizes, int n_in,
                              void* d_out, int out_size) {
    const float* input_aux = (const float*)d_in[0];
    const void*  edges     = d_in[1];
    const float* W_ih      = (const float*)d_in[2];
    const float* W_hh      = (const float*)d_in[3];
    const float* b_ih      = (const float*)d_in[4];
    const float* b_hh      = (const float*)d_in[5];
    const float* W1        = (const float*)d_in[6];
    const float* b1        = (const float*)d_in[7];
    const float* W2        = (const float*)d_in[8];
    const float* b2        = (const float*)d_in[9];
    float* out = (float*)d_out;

    int Nn  = out_size / DIM;
    int seq = in_sizes[0] / (Nn * DIM);
    long long E = (long long)in_sizes[1] / 2;

    float *c, *bsum;
    __half *gates, *hh, *hlo, *wc, *t2h;
    __half *w1thi, *w1tlo, *w2thi, *w2tlo;
    int *eflag, *deg, *off, *cur, *csr_src;
    cudaGetSymbolAddress((void**)&c,       g_c);
    cudaGetSymbolAddress((void**)&gates,   g_gates);
    cudaGetSymbolAddress((void**)&bsum,    g_bsum);
    cudaGetSymbolAddress((void**)&eflag,   g_eflag);
    cudaGetSymbolAddress((void**)&deg,     g_deg);
    cudaGetSymbolAddress((void**)&off,     g_off);
    cudaGetSymbolAddress((void**)&cur,     g_cur);
    cudaGetSymbolAddress((void**)&csr_src, g_csr_src);
    cudaGetSymbolAddress((void**)&hh,      g_hh);
    cudaGetSymbolAddress((void**)&hlo,     g_hlo);
    cudaGetSymbolAddress((void**)&wc,      g_wc);
    cudaGetSymbolAddress((void**)&w1thi,   g_w1thi);
    cudaGetSymbolAddress((void**)&w1tlo,   g_w1tlo);
    cudaGetSymbolAddress((void**)&w2thi,   g_w2thi);
    cudaGetSymbolAddress((void**)&w2tlo,   g_w2tlo);
    cudaGetSymbolAddress((void**)&t2h,     g_t2h);

    __half* t1h = gates;   // reuse gates buffer after LSTM finishes

    int nd = Nn * DIM;
    int eb = 256;
    unsigned eblocks = (unsigned)((E + eb - 1) / eb);

    detect_edge_dtype_k<<<1, 256>>>((const int*)edges, 2 * E, eflag);
    bias_sum_k<<<1, NG>>>(b_ih, b_hh, bsum);
    fill_zero_k<<<(nd + eb - 1) / eb, eb>>>(c, nd);
    fill_zero_k<<<(nd / 2 + eb - 1) / eb, eb>>>((float*)hh, nd / 2);

    // CSR build over dst (shared by both GCN layers)
    fill_zero_int_k<<<(Nn + eb - 1) / eb, eb>>>(deg, Nn);
    hist_k<<<eblocks, eb>>>(edges, E, eflag, Nn, deg);
    scan_k<<<1, 1024>>>(deg, off, Nn);
    copy_int_k<<<(Nn + eb - 1) / eb, eb>>>(off, cur, Nn);
    reorder_k<<<eblocks, eb>>>(edges, E, eflag, Nn, cur, csr_src);

    build_wcat_k<<<(NG * 256 + eb - 1) / eb, eb>>>(W_ih, W_hh, wc);
    build_wt_k<<<(DIM * DIM + eb - 1) / eb, eb>>>(W1, w1thi, w1tlo);
    build_wt_k<<<(DIM * DIM + eb - 1) / eb, eb>>>(W2, w2thi, w2tlo);

    dim3 ggate((Nn + 127) / 128, 4);
    int cell_threads = Nn * 32;
    for (int t = 0; t < seq; ++t) {
        const float* xt = input_aux + (size_t)t * nd;
        gemm_lstm_mma<<<ggate, 256>>>(xt, hh, wc, bsum, gates, Nn);
        lstm_cell_k<<<(cell_threads + eb - 1) / eb, eb>>>(
            gates, c, hh, hlo, Nn, (t == seq - 1) ? 1 : 0);
    }

    dim3 ggcn((Nn + 127) / 128, 1);
    unsigned gblocks = (unsigned)(((long long)Nn * 32 + eb - 1) / eb);

    // GCN layer 1: t1h = h @ W1 (fp16); gather+relu+bias -> hh/hlo (split)
    gemm_gcn_split<<<ggcn, 256>>>(hh, hlo, w1thi, w1tlo, t1h, Nn);
    gather_relu_split_k<<<gblocks, eb>>>(t1h, off, csr_src, b1, hh, hlo, Nn);

    // GCN layer 2: t2h = relu_out @ W2 (fp16); out = gather(t2h) + b2
    gemm_gcn_split<<<ggcn, 256>>>(hh, hlo, w2thi, w2tlo, t2h, Nn);
    gather_bias_k<<<gblocks, eb>>>(t2h, off, csr_src, b2, out, Nn);
}